// round 1
// baseline (speedup 1.0000x reference)
#include <cuda_runtime.h>
#include <math.h>

// Problem constants (fixed by the reference)
#define N_B 8
#define LQ 4096
#define CDIM 768
#define HH 8
#define PP 4
#define DD 96
#define LIN 1728   // 12^3
#define NVOX 12

// ---------------------------------------------------------------------------
// Scratch (static __device__ arrays: allocation-free, graph-capture safe)
// ---------------------------------------------------------------------------
__device__ float g_value[(size_t)N_B * LIN * CDIM];          // (N*Lin, C)  42.5 MB
__device__ float g_off[(size_t)N_B * LQ * HH * PP * 3];      // (N*Lq, 96)  12.6 MB
__device__ float g_att[(size_t)N_B * LQ * HH * PP];          // (N*Lq, 32)   4.2 MB
__device__ float g_samp[(size_t)N_B * LQ * CDIM];            // (N*Lq, C)  100.7 MB

// ---------------------------------------------------------------------------
// Generic smem-tiled SGEMM with bias: C[M,N] = A[M,K] @ B[K,N] + bias[N]
// Requires M % BM == 0, N % BN == 0, K % BK == 0 (guaranteed by our shapes).
// ---------------------------------------------------------------------------
template <int BM, int BN, int BK, int TM, int TN>
__global__ void __launch_bounds__((BM / TM) * (BN / TN))
sgemm_bias(const float* __restrict__ A, const float* __restrict__ B,
           const float* __restrict__ bias, float* __restrict__ C,
           int M, int N, int K)
{
    constexpr int THREADS = (BM / TM) * (BN / TN);
    __shared__ float As[BK][BM];   // A tile stored transposed (k-major)
    __shared__ float Bs[BK][BN];

    const int bm  = blockIdx.y * BM;
    const int bn  = blockIdx.x * BN;
    const int tid = threadIdx.x;
    const int tcol = tid % (BN / TN);
    const int trow = tid / (BN / TN);

    float acc[TM][TN];
    #pragma unroll
    for (int i = 0; i < TM; i++)
        #pragma unroll
        for (int j = 0; j < TN; j++) acc[i][j] = 0.f;

    for (int k0 = 0; k0 < K; k0 += BK) {
        // ---- load A tile (float4 over k) ----
        constexpr int A_V4 = (BM * BK) / (4 * THREADS);
        static_assert((BM * BK) % (4 * THREADS) == 0, "A tile vec");
        #pragma unroll
        for (int t = 0; t < A_V4; t++) {
            int l   = tid + t * THREADS;
            int row = l / (BK / 4);
            int kc  = l % (BK / 4);
            float4 v = *reinterpret_cast<const float4*>(
                &A[(size_t)(bm + row) * K + k0 + kc * 4]);
            As[kc * 4 + 0][row] = v.x;
            As[kc * 4 + 1][row] = v.y;
            As[kc * 4 + 2][row] = v.z;
            As[kc * 4 + 3][row] = v.w;
        }
        // ---- load B tile ----
        if constexpr ((BK * BN) % (4 * THREADS) == 0) {
            constexpr int B_V4 = (BK * BN) / (4 * THREADS);
            #pragma unroll
            for (int t = 0; t < B_V4; t++) {
                int l   = tid + t * THREADS;
                int row = l / (BN / 4);
                int c4  = l % (BN / 4);
                float4 v = *reinterpret_cast<const float4*>(
                    &B[(size_t)(k0 + row) * N + bn + c4 * 4]);
                *reinterpret_cast<float4*>(&Bs[row][c4 * 4]) = v;
            }
        } else {
            constexpr int B_F = (BK * BN) / THREADS;
            #pragma unroll
            for (int t = 0; t < B_F; t++) {
                int l   = tid + t * THREADS;
                int row = l / BN;
                int c   = l % BN;
                Bs[row][c] = B[(size_t)(k0 + row) * N + bn + c];
            }
        }
        __syncthreads();

        // ---- compute ----
        #pragma unroll
        for (int k = 0; k < BK; k++) {
            float ra[TM], rb[TN];
            #pragma unroll
            for (int i = 0; i < TM; i += 4) {
                float4 v = *reinterpret_cast<const float4*>(&As[k][trow * TM + i]);
                ra[i] = v.x; ra[i + 1] = v.y; ra[i + 2] = v.z; ra[i + 3] = v.w;
            }
            if constexpr (TN % 4 == 0) {
                #pragma unroll
                for (int j = 0; j < TN; j += 4) {
                    float4 v = *reinterpret_cast<const float4*>(&Bs[k][tcol * TN + j]);
                    rb[j] = v.x; rb[j + 1] = v.y; rb[j + 2] = v.z; rb[j + 3] = v.w;
                }
            } else {
                #pragma unroll
                for (int j = 0; j < TN; j++) rb[j] = Bs[k][tcol * TN + j];
            }
            #pragma unroll
            for (int i = 0; i < TM; i++)
                #pragma unroll
                for (int j = 0; j < TN; j++)
                    acc[i][j] = fmaf(ra[i], rb[j], acc[i][j]);
        }
        __syncthreads();
    }

    // ---- epilogue: add bias, write ----
    #pragma unroll
    for (int i = 0; i < TM; i++) {
        int r = bm + trow * TM + i;
        #pragma unroll
        for (int j = 0; j < TN; j++) {
            int c = bn + tcol * TN + j;
            C[(size_t)r * N + c] = acc[i][j] + bias[c];
        }
    }
}

// ---------------------------------------------------------------------------
// Sampler: one block per (n, q), 768 threads = one per output channel.
// Threads [0,32) precompute per-(h,p) corner indices / trilinear weights,
// threads [32,40) compute the per-head softmax over P=4.
// Then every thread gathers 4 points x 8 corners of its channel.
// grid_sample semantics: align_corners=False, padding_mode='zeros'.
// ---------------------------------------------------------------------------
__global__ void __launch_bounds__(768) sample_kernel(const float* __restrict__ refpts)
{
    const int bq = blockIdx.x;          // n*4096 + q
    const int n  = bq >> 12;

    __shared__ float s_attn[HH * PP];
    __shared__ int   s_idx[HH * PP][8];
    __shared__ float s_w[HH * PP][8];

    const int tid = threadIdx.x;

    if (tid < HH * PP) {
        const float* off = &g_off[(size_t)bq * (HH * PP * 3) + tid * 3];
        float rx = refpts[(size_t)bq * 3 + 0];
        float ry = refpts[(size_t)bq * 3 + 1];
        float rz = refpts[(size_t)bq * 3 + 2];
        // loc = ref + off/12 ;  grid = 2*loc-1 ;  pixel = ((grid+1)*12 - 1)*0.5 = 12*loc - 0.5
        float x = 12.f * (rx + off[0] * (1.f / 12.f)) - 0.5f;
        float y = 12.f * (ry + off[1] * (1.f / 12.f)) - 0.5f;
        float z = 12.f * (rz + off[2] * (1.f / 12.f)) - 0.5f;
        float x0f = floorf(x), y0f = floorf(y), z0f = floorf(z);
        int x0 = (int)x0f, y0 = (int)y0f, z0 = (int)z0f;
        float fx = x - x0f, fy = y - y0f, fz = z - z0f;
        #pragma unroll
        for (int c = 0; c < 8; c++) {
            int dx = c & 1, dy = (c >> 1) & 1, dz = (c >> 2) & 1;
            int xi = x0 + dx, yi = y0 + dy, zi = z0 + dz;
            float w = (dx ? fx : 1.f - fx) * (dy ? fy : 1.f - fy) * (dz ? fz : 1.f - fz);
            bool valid = (xi >= 0) & (xi < NVOX) & (yi >= 0) & (yi < NVOX) &
                         (zi >= 0) & (zi < NVOX);
            int xc = min(max(xi, 0), NVOX - 1);
            int yc = min(max(yi, 0), NVOX - 1);
            int zc = min(max(zi, 0), NVOX - 1);
            s_idx[tid][c] = (zc * NVOX + yc) * NVOX + xc;
            s_w[tid][c]   = valid ? w : 0.f;
        }
    }
    if (tid >= 32 && tid < 32 + HH) {
        int h = tid - 32;
        const float* lg = &g_att[(size_t)bq * (HH * PP) + h * PP];
        float m = fmaxf(fmaxf(lg[0], lg[1]), fmaxf(lg[2], lg[3]));
        float e0 = expf(lg[0] - m), e1 = expf(lg[1] - m);
        float e2 = expf(lg[2] - m), e3 = expf(lg[3] - m);
        float inv = 1.f / (e0 + e1 + e2 + e3);
        s_attn[h * PP + 0] = e0 * inv;
        s_attn[h * PP + 1] = e1 * inv;
        s_attn[h * PP + 2] = e2 * inv;
        s_attn[h * PP + 3] = e3 * inv;
    }
    __syncthreads();

    const int h = tid / DD;             // head
    const float* vbase = &g_value[(size_t)n * LIN * CDIM + tid];  // + l*CDIM per voxel
    float acc = 0.f;
    #pragma unroll
    for (int p = 0; p < PP; p++) {
        int hp = h * PP + p;
        float a = s_attn[hp];
        float sv = 0.f;
        #pragma unroll
        for (int c = 0; c < 8; c++) {
            sv = fmaf(s_w[hp][c], vbase[(size_t)s_idx[hp][c] * CDIM], sv);
        }
        acc = fmaf(a, sv, acc);
    }
    g_samp[(size_t)bq * CDIM + tid] = acc;
}

// ---------------------------------------------------------------------------
// Launch
// ---------------------------------------------------------------------------
extern "C" void kernel_launch(void* const* d_in, const int* in_sizes, int n_in,
                              void* d_out, int out_size)
{
    const float* query = (const float*)d_in[0];
    const float* refp  = (const float*)d_in[1];
    const float* inp   = (const float*)d_in[2];
    const float* w_val = (const float*)d_in[3];
    const float* b_val = (const float*)d_in[4];
    const float* w_off = (const float*)d_in[5];
    const float* b_off = (const float*)d_in[6];
    const float* w_att = (const float*)d_in[7];
    const float* b_att = (const float*)d_in[8];
    const float* w_out = (const float*)d_in[9];
    const float* b_out = (const float*)d_in[10];
    float* out = (float*)d_out;

    float *pv, *po, *pa, *ps;
    cudaGetSymbolAddress((void**)&pv, g_value);
    cudaGetSymbolAddress((void**)&po, g_off);
    cudaGetSymbolAddress((void**)&pa, g_att);
    cudaGetSymbolAddress((void**)&ps, g_samp);

    const int Mv = N_B * LIN;   // 13824
    const int Mq = N_B * LQ;    // 32768

    // value = input_flatten @ w_val + b_val        (13824 x 768 x 768)
    sgemm_bias<128, 128, 16, 8, 8>
        <<<dim3(CDIM / 128, Mv / 128), 256>>>(inp, w_val, b_val, pv, Mv, CDIM, CDIM);

    // offsets = query @ w_off + b_off              (32768 x 768 x 96)
    sgemm_bias<128, 96, 16, 8, 6>
        <<<dim3(1, Mq / 128), 256>>>(query, w_off, b_off, po, Mq, HH * PP * 3, CDIM);

    // attn logits = query @ w_att + b_att          (32768 x 768 x 32)
    sgemm_bias<128, 32, 16, 8, 4>
        <<<dim3(1, Mq / 128), 128>>>(query, w_att, b_att, pa, Mq, HH * PP, CDIM);

    // softmax + trilinear gather + attention-weighted sum -> g_samp
    sample_kernel<<<Mq, 768>>>(refp);

    // out = g_samp @ w_out + b_out                 (32768 x 768 x 768)
    sgemm_bias<128, 128, 16, 8, 8>
        <<<dim3(CDIM / 128, Mq / 128), 256>>>(ps, w_out, b_out, out, Mq, CDIM, CDIM);
}

// round 3
// speedup vs baseline: 1.7230x; 1.7230x over previous
#include <cuda_runtime.h>
#include <cuda_bf16.h>
#include <math.h>
#include <stdint.h>

// Problem constants
#define N_B 8
#define LQ 4096
#define CDIM 768
#define HH 8
#define PP 4
#define DD 96
#define LIN 1728
#define NVOX 12

// ---------------------------------------------------------------------------
// Scratch (static __device__ arrays: allocation-free, graph-capture safe)
// ---------------------------------------------------------------------------
__device__ float g_value[(size_t)N_B * LIN * CDIM];
__device__ float g_off[(size_t)N_B * LQ * HH * PP * 3];
__device__ float g_att[(size_t)N_B * LQ * HH * PP];
__device__ float g_samp[(size_t)N_B * LQ * CDIM];

// pre-transposed split weights: [N][K] bf16 (hi + residual lo)
__device__ __nv_bfloat16 g_wvh[CDIM * CDIM], g_wvl[CDIM * CDIM];
__device__ __nv_bfloat16 g_woh[CDIM * CDIM], g_wol[CDIM * CDIM];
__device__ __nv_bfloat16 g_wofh[96 * CDIM], g_wofl[96 * CDIM];
__device__ __nv_bfloat16 g_wah[32 * CDIM],  g_wal[32 * CDIM];

// ---------------------------------------------------------------------------
// Small PTX helpers (baseline ISA only: ldmatrix + mma.sync, sm_80+)
// ---------------------------------------------------------------------------
__device__ __forceinline__ uint32_t smem_u32(const void* p) {
    uint32_t a;
    asm("{ .reg .u64 t; cvta.to.shared.u64 t, %1; cvt.u32.u64 %0, t; }" : "=r"(a) : "l"(p));
    return a;
}
__device__ __forceinline__ void ldmx4(uint32_t& r0, uint32_t& r1, uint32_t& r2,
                                      uint32_t& r3, uint32_t addr) {
    asm volatile("ldmatrix.sync.aligned.m8n8.x4.shared.b16 {%0,%1,%2,%3}, [%4];"
                 : "=r"(r0), "=r"(r1), "=r"(r2), "=r"(r3) : "r"(addr));
}
__device__ __forceinline__ void mma16816(float* d, const uint32_t* a, const uint32_t* b) {
    asm volatile(
        "mma.sync.aligned.m16n8k16.row.col.f32.bf16.bf16.f32 "
        "{%0,%1,%2,%3}, {%4,%5,%6,%7}, {%8,%9}, {%0,%1,%2,%3};"
        : "+f"(d[0]), "+f"(d[1]), "+f"(d[2]), "+f"(d[3])
        : "r"(a[0]), "r"(a[1]), "r"(a[2]), "r"(a[3]), "r"(b[0]), "r"(b[1]));
}
__device__ __forceinline__ void split2(float x, float y, uint32_t& hi, uint32_t& lo) {
    __nv_bfloat16 hx = __float2bfloat16(x), hy = __float2bfloat16(y);
    __nv_bfloat16 lx = __float2bfloat16(x - __bfloat162float(hx));
    __nv_bfloat16 ly = __float2bfloat16(y - __bfloat162float(hy));
    hi = (uint32_t)__bfloat16_as_ushort(hx) | ((uint32_t)__bfloat16_as_ushort(hy) << 16);
    lo = (uint32_t)__bfloat16_as_ushort(lx) | ((uint32_t)__bfloat16_as_ushort(ly) << 16);
}

// ---------------------------------------------------------------------------
// Weight transpose + hi/lo bf16 split:  h/l[n*K+k] = split(w[k*N+n])
// ---------------------------------------------------------------------------
__global__ void transpose_split(const float* __restrict__ w, __nv_bfloat16* __restrict__ h,
                                __nv_bfloat16* __restrict__ l, int K, int N)
{
    int idx = blockIdx.x * 256 + threadIdx.x;
    if (idx >= N * K) return;
    int n = idx / K, k = idx % K;
    float v = w[(size_t)k * N + n];
    __nv_bfloat16 hb = __float2bfloat16(v);
    h[idx] = hb;
    l[idx] = __float2bfloat16(v - __bfloat162float(hb));
}

// ---------------------------------------------------------------------------
// Split-bf16 HMMA GEMM: C[M,N] = A[M,K](fp32) @ Bt[N,K]^T + bias
// BM=128, BK=32, 256 threads = 4(m) x 2(n) warps; warp tile 32 x (BN/2).
// 3-term compensated product per tile: AhBh + AhBl + AlBh (fp32 accum).
// Double-buffered smem, padded stride 40 bf16 (80B, ldmatrix conflict-free).
// ---------------------------------------------------------------------------
template <int BN>
__global__ void __launch_bounds__(256)
gemm_mma(const float* __restrict__ A,
         const __nv_bfloat16* __restrict__ Bth, const __nv_bfloat16* __restrict__ Btl,
         const float* __restrict__ bias, float* __restrict__ C,
         int M, int N, int K)
{
    constexpr int BM = 128, BK = 32, SA = 40;     // SA: padded row stride (bf16)
    constexpr int WN = BN / 2, NF = WN / 8;       // n-frags per warp
    constexpr int A_ELE = BM * SA;                // bf16 elems per A split
    constexpr int B_ELE = BN * SA;
    constexpr int BUF = 2 * A_ELE + 2 * B_ELE;    // bf16 elems per buffer
    constexpr int NB4 = BN / 32;                  // uint4 B loads per thread

    extern __shared__ __nv_bfloat16 smbuf[];
    const uint32_t sbase = smem_u32(smbuf);

    const int tid = threadIdx.x;
    const int lane = tid & 31;
    const int wid = tid >> 5;
    const int wm = wid & 3, wn = wid >> 2;
    const int bm = blockIdx.y * BM, bn = blockIdx.x * BN;
    const int nch = K / BK;

    float acc[2][NF][4];
    #pragma unroll
    for (int i = 0; i < 2; i++)
        #pragma unroll
        for (int j = 0; j < NF; j++)
            #pragma unroll
            for (int q = 0; q < 4; q++) acc[i][j][q] = 0.f;

    float4 aR[4];
    uint4  bR[NB4];

    // decoded indices for the cooperative loads (constant per thread)
    // A: 4 float4 per thread covering 128x32 fp32
    // B: NB4 uint4 per thread covering 2 splits x BN x 32 bf16
    auto loadG = [&](int c) {
        const int k0 = c * BK;
        #pragma unroll
        for (int t = 0; t < 4; t++) {
            int l = t * 256 + tid;
            int row = l >> 3, c4 = l & 7;
            aR[t] = *reinterpret_cast<const float4*>(&A[(size_t)(bm + row) * K + k0 + c4 * 4]);
        }
        #pragma unroll
        for (int t = 0; t < NB4; t++) {
            int l = t * 256 + tid;
            int split = l / (4 * BN);
            int rr = (l % (4 * BN)) >> 2;
            int q = l & 3;
            const __nv_bfloat16* src = split ? Btl : Bth;
            bR[t] = *reinterpret_cast<const uint4*>(&src[(size_t)(bn + rr) * K + k0 + q * 8]);
        }
    };
    auto stsS = [&](int buf) {
        const uint32_t base = sbase + (uint32_t)buf * BUF * 2;
        #pragma unroll
        for (int t = 0; t < 4; t++) {
            int l = t * 256 + tid;
            int row = l >> 3, c4 = l & 7;
            uint32_t h0, l0, h1, l1;
            split2(aR[t].x, aR[t].y, h0, l0);
            split2(aR[t].z, aR[t].w, h1, l1);
            uint32_t off = (uint32_t)(row * SA + c4 * 4) * 2;
            asm volatile("st.shared.v2.b32 [%0], {%1,%2};" :: "r"(base + off), "r"(h0), "r"(h1) : "memory");
            asm volatile("st.shared.v2.b32 [%0], {%1,%2};" :: "r"(base + A_ELE * 2 + off), "r"(l0), "r"(l1) : "memory");
        }
        #pragma unroll
        for (int t = 0; t < NB4; t++) {
            int l = t * 256 + tid;
            int split = l / (4 * BN);
            int rr = (l % (4 * BN)) >> 2;
            int q = l & 3;
            uint32_t off = (uint32_t)(2 * A_ELE + split * B_ELE + rr * SA + q * 8) * 2;
            asm volatile("st.shared.v4.b32 [%0], {%1,%2,%3,%4};"
                         :: "r"(base + off), "r"(bR[t].x), "r"(bR[t].y), "r"(bR[t].z), "r"(bR[t].w) : "memory");
        }
    };
    auto compute = [&](int buf) {
        const uint32_t base = sbase + (uint32_t)buf * BUF * 2;
        const uint32_t aH = base;
        const uint32_t aL = base + A_ELE * 2;
        const uint32_t bH = base + 4 * A_ELE;          // (2*A_ELE)*2 bytes
        const uint32_t bL = base + 4 * A_ELE + B_ELE * 2;
        #pragma unroll
        for (int s = 0; s < 2; s++) {                  // two k16 steps per BK=32
            uint32_t ah[2][4], al[2][4], bh[NF][2], bl[NF][2];
            #pragma unroll
            for (int i = 0; i < 2; i++) {
                uint32_t row = wm * 32 + i * 16 + (lane & 15);
                uint32_t off = (row * SA + s * 16 + (lane >> 4) * 8) * 2;
                ldmx4(ah[i][0], ah[i][1], ah[i][2], ah[i][3], aH + off);
                ldmx4(al[i][0], al[i][1], al[i][2], al[i][3], aL + off);
            }
            #pragma unroll
            for (int j = 0; j < NF; j += 2) {
                uint32_t row = wn * WN + j * 8 + (lane & 7) + ((lane & 16) ? 8 : 0);
                uint32_t off = (row * SA + s * 16 + ((lane >> 3) & 1) * 8) * 2;
                uint32_t r0, r1, r2, r3;
                ldmx4(r0, r1, r2, r3, bH + off);
                bh[j][0] = r0; bh[j][1] = r1; bh[j + 1][0] = r2; bh[j + 1][1] = r3;
                ldmx4(r0, r1, r2, r3, bL + off);
                bl[j][0] = r0; bl[j][1] = r1; bl[j + 1][0] = r2; bl[j + 1][1] = r3;
            }
            #pragma unroll
            for (int i = 0; i < 2; i++)
                #pragma unroll
                for (int j = 0; j < NF; j++) {
                    mma16816(acc[i][j], ah[i], bh[j]);
                    mma16816(acc[i][j], ah[i], bl[j]);
                    mma16816(acc[i][j], al[i], bh[j]);
                }
        }
    };

    loadG(0);
    stsS(0);
    __syncthreads();
    for (int c = 0; c < nch; c++) {
        if (c + 1 < nch) loadG(c + 1);
        compute(c & 1);
        if (c + 1 < nch) stsS((c + 1) & 1);
        __syncthreads();
    }

    // Epilogue: C frag layout -> direct float2 stores + bias
    #pragma unroll
    for (int i = 0; i < 2; i++) {
        int r0 = bm + wm * 32 + i * 16 + (lane >> 2);
        #pragma unroll
        for (int j = 0; j < NF; j++) {
            int col = bn + wn * WN + j * 8 + (lane & 3) * 2;
            float b0 = bias[col], b1 = bias[col + 1];
            float2 v0 = make_float2(acc[i][j][0] + b0, acc[i][j][1] + b1);
            float2 v1 = make_float2(acc[i][j][2] + b0, acc[i][j][3] + b1);
            *reinterpret_cast<float2*>(&C[(size_t)r0 * N + col]) = v0;
            *reinterpret_cast<float2*>(&C[(size_t)(r0 + 8) * N + col]) = v1;
        }
    }
}

// ---------------------------------------------------------------------------
// Sampler (unchanged)
// ---------------------------------------------------------------------------
__global__ void __launch_bounds__(768) sample_kernel(const float* __restrict__ refpts)
{
    const int bq = blockIdx.x;
    const int n = bq >> 12;

    __shared__ float s_attn[HH * PP];
    __shared__ int s_idx[HH * PP][8];
    __shared__ float s_w[HH * PP][8];

    const int tid = threadIdx.x;

    if (tid < HH * PP) {
        const float* off = &g_off[(size_t)bq * (HH * PP * 3) + tid * 3];
        float rx = refpts[(size_t)bq * 3 + 0];
        float ry = refpts[(size_t)bq * 3 + 1];
        float rz = refpts[(size_t)bq * 3 + 2];
        float x = 12.f * (rx + off[0] * (1.f / 12.f)) - 0.5f;
        float y = 12.f * (ry + off[1] * (1.f / 12.f)) - 0.5f;
        float z = 12.f * (rz + off[2] * (1.f / 12.f)) - 0.5f;
        float x0f = floorf(x), y0f = floorf(y), z0f = floorf(z);
        int x0 = (int)x0f, y0 = (int)y0f, z0 = (int)z0f;
        float fx = x - x0f, fy = y - y0f, fz = z - z0f;
        #pragma unroll
        for (int c = 0; c < 8; c++) {
            int dx = c & 1, dy = (c >> 1) & 1, dz = (c >> 2) & 1;
            int xi = x0 + dx, yi = y0 + dy, zi = z0 + dz;
            float w = (dx ? fx : 1.f - fx) * (dy ? fy : 1.f - fy) * (dz ? fz : 1.f - fz);
            bool valid = (xi >= 0) & (xi < NVOX) & (yi >= 0) & (yi < NVOX) &
                         (zi >= 0) & (zi < NVOX);
            int xc = min(max(xi, 0), NVOX - 1);
            int yc = min(max(yi, 0), NVOX - 1);
            int zc = min(max(zi, 0), NVOX - 1);
            s_idx[tid][c] = (zc * NVOX + yc) * NVOX + xc;
            s_w[tid][c] = valid ? w : 0.f;
        }
    }
    if (tid >= 32 && tid < 32 + HH) {
        int h = tid - 32;
        const float* lg = &g_att[(size_t)bq * (HH * PP) + h * PP];
        float m = fmaxf(fmaxf(lg[0], lg[1]), fmaxf(lg[2], lg[3]));
        float e0 = expf(lg[0] - m), e1 = expf(lg[1] - m);
        float e2 = expf(lg[2] - m), e3 = expf(lg[3] - m);
        float inv = 1.f / (e0 + e1 + e2 + e3);
        s_attn[h * PP + 0] = e0 * inv;
        s_attn[h * PP + 1] = e1 * inv;
        s_attn[h * PP + 2] = e2 * inv;
        s_attn[h * PP + 3] = e3 * inv;
    }
    __syncthreads();

    const int h = tid / DD;
    const float* vbase = &g_value[(size_t)n * LIN * CDIM + tid];
    float acc = 0.f;
    #pragma unroll
    for (int p = 0; p < PP; p++) {
        int hp = h * PP + p;
        float a = s_attn[hp];
        float sv = 0.f;
        #pragma unroll
        for (int c = 0; c < 8; c++) {
            sv = fmaf(s_w[hp][c], vbase[(size_t)s_idx[hp][c] * CDIM], sv);
        }
        acc = fmaf(a, sv, acc);
    }
    g_samp[(size_t)bq * CDIM + tid] = acc;
}

// ---------------------------------------------------------------------------
// Launch
// ---------------------------------------------------------------------------
extern "C" void kernel_launch(void* const* d_in, const int* in_sizes, int n_in,
                              void* d_out, int out_size)
{
    const float* query = (const float*)d_in[0];
    const float* refp  = (const float*)d_in[1];
    const float* inp   = (const float*)d_in[2];
    const float* w_val = (const float*)d_in[3];
    const float* b_val = (const float*)d_in[4];
    const float* w_off = (const float*)d_in[5];
    const float* b_off = (const float*)d_in[6];
    const float* w_att = (const float*)d_in[7];
    const float* b_att = (const float*)d_in[8];
    const float* w_out = (const float*)d_in[9];
    const float* b_out = (const float*)d_in[10];
    float* out = (float*)d_out;

    float *pv, *po, *pa, *ps;
    cudaGetSymbolAddress((void**)&pv, g_value);
    cudaGetSymbolAddress((void**)&po, g_off);
    cudaGetSymbolAddress((void**)&pa, g_att);
    cudaGetSymbolAddress((void**)&ps, g_samp);
    __nv_bfloat16 *wvh, *wvl, *woh, *wol, *wofh, *wofl, *wah, *wal;
    cudaGetSymbolAddress((void**)&wvh, g_wvh);
    cudaGetSymbolAddress((void**)&wvl, g_wvl);
    cudaGetSymbolAddress((void**)&woh, g_woh);
    cudaGetSymbolAddress((void**)&wol, g_wol);
    cudaGetSymbolAddress((void**)&wofh, g_wofh);
    cudaGetSymbolAddress((void**)&wofl, g_wofl);
    cudaGetSymbolAddress((void**)&wah, g_wah);
    cudaGetSymbolAddress((void**)&wal, g_wal);

    // dynamic smem: 2 buffers x (2*128*40 + 2*BN*40) bf16 elems x 2 bytes
    const int SMEM128 = 2 * (2 * 128 * 40 + 2 * 128 * 40) * 2;  // 81920
    const int SMEM96  = 2 * (2 * 128 * 40 + 2 * 96 * 40) * 2;   // 71680
    const int SMEM32  = 2 * (2 * 128 * 40 + 2 * 32 * 40) * 2;   // 51200
    cudaFuncSetAttribute(gemm_mma<128>, cudaFuncAttributeMaxDynamicSharedMemorySize, SMEM128);
    cudaFuncSetAttribute(gemm_mma<96>,  cudaFuncAttributeMaxDynamicSharedMemorySize, SMEM96);
    cudaFuncSetAttribute(gemm_mma<32>,  cudaFuncAttributeMaxDynamicSharedMemorySize, SMEM32);

    const int Mv = N_B * LIN;   // 13824
    const int Mq = N_B * LQ;    // 32768

    // weight transpose + split
    transpose_split<<<(CDIM * CDIM + 255) / 256, 256>>>(w_val, wvh, wvl, CDIM, CDIM);
    transpose_split<<<(CDIM * 96 + 255) / 256, 256>>>(w_off, wofh, wofl, CDIM, 96);
    transpose_split<<<(CDIM * 32 + 255) / 256, 256>>>(w_att, wah, wal, CDIM, 32);
    transpose_split<<<(CDIM * CDIM + 255) / 256, 256>>>(w_out, woh, wol, CDIM, CDIM);

    // value = input_flatten @ w_val + b_val   (13824 x 768 x 768)
    gemm_mma<128><<<dim3(CDIM / 128, Mv / 128), 256, SMEM128>>>(inp, wvh, wvl, b_val, pv, Mv, CDIM, CDIM);
    // offsets = query @ w_off + b_off         (32768 x 96 x 768)
    gemm_mma<96><<<dim3(1, Mq / 128), 256, SMEM96>>>(query, wofh, wofl, b_off, po, Mq, 96, CDIM);
    // attn logits = query @ w_att + b_att     (32768 x 32 x 768)
    gemm_mma<32><<<dim3(1, Mq / 128), 256, SMEM32>>>(query, wah, wal, b_att, pa, Mq, 32, CDIM);
    // softmax + trilinear gather + attention-weighted sum -> g_samp
    sample_kernel<<<Mq, 768>>>(refp);
    // out = g_samp @ w_out + b_out            (32768 x 768 x 768)
    gemm_mma<128><<<dim3(CDIM / 128, Mq / 128), 256, SMEM128>>>(ps, woh, wol, b_out, out, Mq, CDIM, CDIM);
}

// round 4
// speedup vs baseline: 2.3444x; 1.3607x over previous
#include <cuda_runtime.h>
#include <cuda_bf16.h>
#include <math.h>
#include <stdint.h>

// Problem constants
#define N_B 8
#define LQ 4096
#define CDIM 768
#define HH 8
#define PP 4
#define DD 96
#define LIN 1728
#define NVOX 12

// ---------------------------------------------------------------------------
// Scratch (static __device__ arrays: allocation-free, graph-capture safe)
// ---------------------------------------------------------------------------
__device__ float g_value[(size_t)N_B * LIN * CDIM];             // 42.5 MB
__device__ float g_oa[(size_t)N_B * LQ * 128];                  // fused offsets(96)+attn(32)
__device__ __nv_bfloat16 g_samph[(size_t)N_B * LQ * CDIM];      // sampled hi
__device__ __nv_bfloat16 g_sampl[(size_t)N_B * LQ * CDIM];      // sampled lo

// pre-transposed split weights: [N][K] bf16 (hi + residual lo)
__device__ __nv_bfloat16 g_wvh[CDIM * CDIM], g_wvl[CDIM * CDIM];
__device__ __nv_bfloat16 g_woh[CDIM * CDIM], g_wol[CDIM * CDIM];
__device__ __nv_bfloat16 g_woah[128 * CDIM], g_woal[128 * CDIM]; // rows 0..95 off, 96..127 att

// ---------------------------------------------------------------------------
// PTX helpers (baseline ISA: ldmatrix + mma.sync + cp.async, sm_80+)
// ---------------------------------------------------------------------------
__device__ __forceinline__ uint32_t smem_u32(const void* p) {
    uint32_t a;
    asm("{ .reg .u64 t; cvta.to.shared.u64 t, %1; cvt.u32.u64 %0, t; }" : "=r"(a) : "l"(p));
    return a;
}
__device__ __forceinline__ void ldmx4(uint32_t& r0, uint32_t& r1, uint32_t& r2,
                                      uint32_t& r3, uint32_t addr) {
    asm volatile("ldmatrix.sync.aligned.m8n8.x4.shared.b16 {%0,%1,%2,%3}, [%4];"
                 : "=r"(r0), "=r"(r1), "=r"(r2), "=r"(r3) : "r"(addr));
}
__device__ __forceinline__ void mma16816(float* d, const uint32_t* a, const uint32_t* b) {
    asm volatile(
        "mma.sync.aligned.m16n8k16.row.col.f32.bf16.bf16.f32 "
        "{%0,%1,%2,%3}, {%4,%5,%6,%7}, {%8,%9}, {%0,%1,%2,%3};"
        : "+f"(d[0]), "+f"(d[1]), "+f"(d[2]), "+f"(d[3])
        : "r"(a[0]), "r"(a[1]), "r"(a[2]), "r"(a[3]), "r"(b[0]), "r"(b[1]));
}
__device__ __forceinline__ void cpasync16(uint32_t dst, const void* src) {
    asm volatile("cp.async.cg.shared.global [%0], [%1], 16;" :: "r"(dst), "l"(src));
}
#define CP_COMMIT() asm volatile("cp.async.commit_group;" ::: "memory")
#define CP_WAIT0()  asm volatile("cp.async.wait_group 0;" ::: "memory")
#define CP_WAIT1()  asm volatile("cp.async.wait_group 1;" ::: "memory")

__device__ __forceinline__ void split2(float x, float y, uint32_t& hi, uint32_t& lo) {
    __nv_bfloat16 hx = __float2bfloat16(x), hy = __float2bfloat16(y);
    __nv_bfloat16 lx = __float2bfloat16(x - __bfloat162float(hx));
    __nv_bfloat16 ly = __float2bfloat16(y - __bfloat162float(hy));
    hi = (uint32_t)__bfloat16_as_ushort(hx) | ((uint32_t)__bfloat16_as_ushort(hy) << 16);
    lo = (uint32_t)__bfloat16_as_ushort(lx) | ((uint32_t)__bfloat16_as_ushort(ly) << 16);
}

// ---------------------------------------------------------------------------
// Weight transpose + hi/lo bf16 split:  h/l[n*K+k] = split(w[k*N+n])
// ---------------------------------------------------------------------------
__global__ void transpose_split(const float* __restrict__ w, __nv_bfloat16* __restrict__ h,
                                __nv_bfloat16* __restrict__ l, int K, int N)
{
    int idx = blockIdx.x * 256 + threadIdx.x;
    if (idx >= N * K) return;
    int n = idx / K, k = idx % K;
    float v = w[(size_t)k * N + n];
    __nv_bfloat16 hb = __float2bfloat16(v);
    h[idx] = hb;
    l[idx] = __float2bfloat16(v - __bfloat162float(hb));
}

// ---------------------------------------------------------------------------
// Split-bf16 HMMA GEMM: C[M,128-tileN] = A[M,K] @ Bt[N,K]^T + bias
// BM=128, BN=128, BK=32, 256 threads = 4(m) x 2(n) warps; warp tile 32x64.
// PRE=false: A fp32, converted inline (LDG->split->STS); B via cp.async.
// PRE=true : A pre-split bf16; A and B both via cp.async (no STS stage).
// ---------------------------------------------------------------------------
template <bool PRE>
__global__ void __launch_bounds__(256)
gemm_mma(const float* __restrict__ A32,
         const __nv_bfloat16* __restrict__ Ah, const __nv_bfloat16* __restrict__ Al,
         const __nv_bfloat16* __restrict__ Bth, const __nv_bfloat16* __restrict__ Btl,
         const float* __restrict__ bias, const float* __restrict__ bias2, int nsplit,
         float* __restrict__ C, int M, int N, int K)
{
    constexpr int BM = 128, BN = 128, BK = 32, SA = 40;
    constexpr int WN = BN / 2, NF = WN / 8;        // 8 n-frags per warp
    constexpr int A_ELE = BM * SA;
    constexpr int B_ELE = BN * SA;
    constexpr int BUF = 2 * A_ELE + 2 * B_ELE;     // bf16 elems per buffer

    extern __shared__ __nv_bfloat16 smbuf[];
    const uint32_t sbase = smem_u32(smbuf);

    const int tid = threadIdx.x;
    const int lane = tid & 31;
    const int wid = tid >> 5;
    const int wm = wid & 3, wn = wid >> 2;
    const int bm = blockIdx.y * BM, bn = blockIdx.x * BN;
    const int nch = K / BK;

    float acc[2][NF][4];
    #pragma unroll
    for (int i = 0; i < 2; i++)
        #pragma unroll
        for (int j = 0; j < NF; j++)
            #pragma unroll
            for (int q = 0; q < 4; q++) acc[i][j][q] = 0.f;

    float4 aR[4];

    auto asyncB = [&](int c, int buf) {
        const int k0 = c * BK;
        const uint32_t base = sbase + (uint32_t)buf * BUF * 2;
        #pragma unroll
        for (int t = 0; t < 4; t++) {
            int l = t * 256 + tid;
            int split = l >> 9;            // /512
            int rr = (l & 511) >> 2;
            int q = l & 3;
            const __nv_bfloat16* src = split ? Btl : Bth;
            uint32_t dst = base + (uint32_t)(2 * A_ELE + split * B_ELE + rr * SA + q * 8) * 2;
            cpasync16(dst, &src[(size_t)(bn + rr) * K + k0 + q * 8]);
        }
    };
    auto asyncA = [&](int c, int buf) {    // PRE only
        const int k0 = c * BK;
        const uint32_t base = sbase + (uint32_t)buf * BUF * 2;
        #pragma unroll
        for (int t = 0; t < 4; t++) {
            int l = t * 256 + tid;
            int split = l >> 9;
            int rr = (l & 511) >> 2;
            int q = l & 3;
            const __nv_bfloat16* src = split ? Al : Ah;
            uint32_t dst = base + (uint32_t)(split * A_ELE + rr * SA + q * 8) * 2;
            cpasync16(dst, &src[(size_t)(bm + rr) * K + k0 + q * 8]);
        }
    };
    auto loadA = [&](int c) {              // !PRE
        const int k0 = c * BK;
        #pragma unroll
        for (int t = 0; t < 4; t++) {
            int l = t * 256 + tid;
            int row = l >> 3, c4 = l & 7;
            aR[t] = *reinterpret_cast<const float4*>(&A32[(size_t)(bm + row) * K + k0 + c4 * 4]);
        }
    };
    auto stsA = [&](int buf) {             // !PRE
        const uint32_t base = sbase + (uint32_t)buf * BUF * 2;
        #pragma unroll
        for (int t = 0; t < 4; t++) {
            int l = t * 256 + tid;
            int row = l >> 3, c4 = l & 7;
            uint32_t h0, l0, h1, l1;
            split2(aR[t].x, aR[t].y, h0, l0);
            split2(aR[t].z, aR[t].w, h1, l1);
            uint32_t off = (uint32_t)(row * SA + c4 * 4) * 2;
            asm volatile("st.shared.v2.b32 [%0], {%1,%2};" :: "r"(base + off), "r"(h0), "r"(h1) : "memory");
            asm volatile("st.shared.v2.b32 [%0], {%1,%2};" :: "r"(base + A_ELE * 2 + off), "r"(l0), "r"(l1) : "memory");
        }
    };
    auto compute = [&](int buf) {
        const uint32_t base = sbase + (uint32_t)buf * BUF * 2;
        const uint32_t aH = base;
        const uint32_t aL = base + A_ELE * 2;
        const uint32_t bH = base + 4 * A_ELE;
        const uint32_t bL = base + 4 * A_ELE + B_ELE * 2;
        #pragma unroll
        for (int s = 0; s < 2; s++) {
            uint32_t ah[2][4], al[2][4], bh[NF][2], bl[NF][2];
            #pragma unroll
            for (int i = 0; i < 2; i++) {
                uint32_t row = wm * 32 + i * 16 + (lane & 15);
                uint32_t off = (row * SA + s * 16 + (lane >> 4) * 8) * 2;
                ldmx4(ah[i][0], ah[i][1], ah[i][2], ah[i][3], aH + off);
                ldmx4(al[i][0], al[i][1], al[i][2], al[i][3], aL + off);
            }
            #pragma unroll
            for (int j = 0; j < NF; j += 2) {
                uint32_t row = wn * WN + j * 8 + (lane & 7) + ((lane & 16) ? 8 : 0);
                uint32_t off = (row * SA + s * 16 + ((lane >> 3) & 1) * 8) * 2;
                uint32_t r0, r1, r2, r3;
                ldmx4(r0, r1, r2, r3, bH + off);
                bh[j][0] = r0; bh[j][1] = r1; bh[j + 1][0] = r2; bh[j + 1][1] = r3;
                ldmx4(r0, r1, r2, r3, bL + off);
                bl[j][0] = r0; bl[j][1] = r1; bl[j + 1][0] = r2; bl[j + 1][1] = r3;
            }
            #pragma unroll
            for (int i = 0; i < 2; i++)
                #pragma unroll
                for (int j = 0; j < NF; j++) {
                    mma16816(acc[i][j], ah[i], bh[j]);
                    mma16816(acc[i][j], ah[i], bl[j]);
                    mma16816(acc[i][j], al[i], bh[j]);
                }
        }
    };

    if constexpr (PRE) {
        asyncA(0, 0); asyncB(0, 0); CP_COMMIT();
        for (int c = 0; c < nch; c++) {
            if (c + 1 < nch) { asyncA(c + 1, (c + 1) & 1); asyncB(c + 1, (c + 1) & 1); CP_COMMIT(); }
            if (c + 1 < nch) CP_WAIT1(); else CP_WAIT0();
            __syncthreads();
            compute(c & 1);
            __syncthreads();
        }
    } else {
        asyncB(0, 0); CP_COMMIT();
        loadA(0);
        CP_WAIT0();
        stsA(0);
        __syncthreads();
        for (int c = 0; c < nch; c++) {
            if (c + 1 < nch) { asyncB(c + 1, (c + 1) & 1); CP_COMMIT(); loadA(c + 1); }
            compute(c & 1);
            if (c + 1 < nch) { CP_WAIT0(); stsA((c + 1) & 1); }
            __syncthreads();
        }
    }

    // Epilogue: direct float2 stores + (possibly concatenated) bias
    #pragma unroll
    for (int i = 0; i < 2; i++) {
        int r0 = bm + wm * 32 + i * 16 + (lane >> 2);
        #pragma unroll
        for (int j = 0; j < NF; j++) {
            int col = bn + wn * WN + j * 8 + (lane & 3) * 2;
            float b0 = (col < nsplit) ? bias[col] : bias2[col - nsplit];
            float b1 = (col + 1 < nsplit) ? bias[col + 1] : bias2[col + 1 - nsplit];
            float2 v0 = make_float2(acc[i][j][0] + b0, acc[i][j][1] + b1);
            float2 v1 = make_float2(acc[i][j][2] + b0, acc[i][j][3] + b1);
            *reinterpret_cast<float2*>(&C[(size_t)r0 * N + col]) = v0;
            *reinterpret_cast<float2*>(&C[(size_t)(r0 + 8) * N + col]) = v1;
        }
    }
}

// ---------------------------------------------------------------------------
// Sampler: 768 threads = 4 queries x 192 gather threads (float4 = 4 channels).
// Reads fused g_oa (offsets cols 0..95, attn logits 96..127).
// Writes pre-split bf16 hi/lo for the out-projection GEMM.
// ---------------------------------------------------------------------------
__global__ void __launch_bounds__(768) sample_kernel(const float* __restrict__ refpts)
{
    const int b0 = blockIdx.x * 4;

    __shared__ float s_attn[4][32];
    __shared__ int   s_idx[4][32][8];
    __shared__ float s_w[4][32][8];

    const int tid = threadIdx.x;

    if (tid < 128) {
        int qi = tid >> 5, hp = tid & 31;
        int bq = b0 + qi;
        const float* oa = &g_oa[(size_t)bq * 128 + hp * 3];
        float rx = refpts[(size_t)bq * 3 + 0];
        float ry = refpts[(size_t)bq * 3 + 1];
        float rz = refpts[(size_t)bq * 3 + 2];
        // pixel = 12*(ref + off/12) - 0.5 = 12*ref + off - 0.5
        float x = 12.f * rx + oa[0] - 0.5f;
        float y = 12.f * ry + oa[1] - 0.5f;
        float z = 12.f * rz + oa[2] - 0.5f;
        float x0f = floorf(x), y0f = floorf(y), z0f = floorf(z);
        int x0 = (int)x0f, y0 = (int)y0f, z0 = (int)z0f;
        float fx = x - x0f, fy = y - y0f, fz = z - z0f;
        #pragma unroll
        for (int c = 0; c < 8; c++) {
            int dx = c & 1, dy = (c >> 1) & 1, dz = (c >> 2) & 1;
            int xi = x0 + dx, yi = y0 + dy, zi = z0 + dz;
            float w = (dx ? fx : 1.f - fx) * (dy ? fy : 1.f - fy) * (dz ? fz : 1.f - fz);
            bool valid = (xi >= 0) & (xi < NVOX) & (yi >= 0) & (yi < NVOX) &
                         (zi >= 0) & (zi < NVOX);
            int xc = min(max(xi, 0), NVOX - 1);
            int yc = min(max(yi, 0), NVOX - 1);
            int zc = min(max(zi, 0), NVOX - 1);
            s_idx[qi][hp][c] = (zc * NVOX + yc) * NVOX + xc;
            s_w[qi][hp][c] = valid ? w : 0.f;
        }
    }
    if (tid >= 128 && tid < 160) {
        int idx = tid - 128;
        int qi = idx >> 3, h = idx & 7;
        const float* lg = &g_oa[(size_t)(b0 + qi) * 128 + 96 + h * 4];
        float m = fmaxf(fmaxf(lg[0], lg[1]), fmaxf(lg[2], lg[3]));
        float e0 = expf(lg[0] - m), e1 = expf(lg[1] - m);
        float e2 = expf(lg[2] - m), e3 = expf(lg[3] - m);
        float inv = 1.f / (e0 + e1 + e2 + e3);
        s_attn[qi][h * 4 + 0] = e0 * inv;
        s_attn[qi][h * 4 + 1] = e1 * inv;
        s_attn[qi][h * 4 + 2] = e2 * inv;
        s_attn[qi][h * 4 + 3] = e3 * inv;
    }
    __syncthreads();

    const int qi = tid / 192;
    const int tt = tid % 192;
    const int h = tt / 24;
    const int c4 = (tt % 24) * 4;
    const int bq = b0 + qi;
    const int n = bq >> 12;
    const float* vbase = &g_value[(size_t)n * LIN * CDIM + h * DD + c4];

    float4 acc = make_float4(0.f, 0.f, 0.f, 0.f);
    #pragma unroll
    for (int p = 0; p < PP; p++) {
        int hp = h * PP + p;
        float a = s_attn[qi][hp];
        float4 sv = make_float4(0.f, 0.f, 0.f, 0.f);
        #pragma unroll
        for (int c = 0; c < 8; c++) {
            float w = s_w[qi][hp][c];
            const float4 v = *reinterpret_cast<const float4*>(
                vbase + (size_t)s_idx[qi][hp][c] * CDIM);
            sv.x = fmaf(w, v.x, sv.x);
            sv.y = fmaf(w, v.y, sv.y);
            sv.z = fmaf(w, v.z, sv.z);
            sv.w = fmaf(w, v.w, sv.w);
        }
        acc.x = fmaf(a, sv.x, acc.x);
        acc.y = fmaf(a, sv.y, acc.y);
        acc.z = fmaf(a, sv.z, acc.z);
        acc.w = fmaf(a, sv.w, acc.w);
    }

    // split to hi/lo bf16 and store (8B each)
    uint32_t h01, l01, h23, l23;
    split2(acc.x, acc.y, h01, l01);
    split2(acc.z, acc.w, h23, l23);
    size_t o = (size_t)bq * CDIM + h * DD + c4;
    *reinterpret_cast<uint2*>(&g_samph[o]) = make_uint2(h01, h23);
    *reinterpret_cast<uint2*>(&g_sampl[o]) = make_uint2(l01, l23);
}

// ---------------------------------------------------------------------------
// Launch
// ---------------------------------------------------------------------------
extern "C" void kernel_launch(void* const* d_in, const int* in_sizes, int n_in,
                              void* d_out, int out_size)
{
    const float* query = (const float*)d_in[0];
    const float* refp  = (const float*)d_in[1];
    const float* inp   = (const float*)d_in[2];
    const float* w_val = (const float*)d_in[3];
    const float* b_val = (const float*)d_in[4];
    const float* w_off = (const float*)d_in[5];
    const float* b_off = (const float*)d_in[6];
    const float* w_att = (const float*)d_in[7];
    const float* b_att = (const float*)d_in[8];
    const float* w_out = (const float*)d_in[9];
    const float* b_out = (const float*)d_in[10];
    float* out = (float*)d_out;

    float *pv, *poa;
    cudaGetSymbolAddress((void**)&pv, g_value);
    cudaGetSymbolAddress((void**)&poa, g_oa);
    __nv_bfloat16 *sph, *spl, *wvh, *wvl, *woh, *wol, *woah, *woal;
    cudaGetSymbolAddress((void**)&sph, g_samph);
    cudaGetSymbolAddress((void**)&spl, g_sampl);
    cudaGetSymbolAddress((void**)&wvh, g_wvh);
    cudaGetSymbolAddress((void**)&wvl, g_wvl);
    cudaGetSymbolAddress((void**)&woh, g_woh);
    cudaGetSymbolAddress((void**)&wol, g_wol);
    cudaGetSymbolAddress((void**)&woah, g_woah);
    cudaGetSymbolAddress((void**)&woal, g_woal);

    // dynamic smem: 2 buffers x 4 arrays x 128 x 40 bf16
    const int SMEM = 2 * (2 * 128 * 40 + 2 * 128 * 40) * 2;    // 81920
    cudaFuncSetAttribute(gemm_mma<false>, cudaFuncAttributeMaxDynamicSharedMemorySize, SMEM);
    cudaFuncSetAttribute(gemm_mma<true>,  cudaFuncAttributeMaxDynamicSharedMemorySize, SMEM);

    const int Mv = N_B * LIN;   // 13824
    const int Mq = N_B * LQ;    // 32768

    // weight transpose + split (off+att fused into one 128-row Bt)
    transpose_split<<<(CDIM * CDIM + 255) / 256, 256>>>(w_val, wvh, wvl, CDIM, CDIM);
    transpose_split<<<(CDIM * 96 + 255) / 256, 256>>>(w_off, woah, woal, CDIM, 96);
    transpose_split<<<(CDIM * 32 + 255) / 256, 256>>>(w_att, woah + 96 * CDIM, woal + 96 * CDIM, CDIM, 32);
    transpose_split<<<(CDIM * CDIM + 255) / 256, 256>>>(w_out, woh, wol, CDIM, CDIM);

    // value = input_flatten @ w_val + b_val   (13824 x 768 x 768)
    gemm_mma<false><<<dim3(CDIM / 128, Mv / 128), 256, SMEM>>>(
        inp, nullptr, nullptr, wvh, wvl, b_val, b_val, CDIM, pv, Mv, CDIM, CDIM);

    // fused [offsets | attn] = query @ [w_off | w_att] + [b_off | b_att]  (32768 x 128 x 768)
    gemm_mma<false><<<dim3(1, Mq / 128), 256, SMEM>>>(
        query, nullptr, nullptr, woah, woal, b_off, b_att, 96, poa, Mq, 128, CDIM);

    // softmax + trilinear gather -> pre-split bf16 sampled output
    sample_kernel<<<Mq / 4, 768>>>(refp);

    // out = samp @ w_out + b_out              (32768 x 768 x 768), pre-split A
    gemm_mma<true><<<dim3(CDIM / 128, Mq / 128), 256, SMEM>>>(
        nullptr, sph, spl, woh, wol, b_out, b_out, CDIM, out, Mq, CDIM, CDIM);
}

// round 5
// speedup vs baseline: 4.1437x; 1.7675x over previous
#include <cuda_runtime.h>
#include <cuda_fp16.h>
#include <math.h>
#include <stdint.h>

// Problem constants
#define N_B 8
#define LQ 4096
#define CDIM 768
#define HH 8
#define PP 4
#define DD 96
#define LIN 1728
#define NVOX 12

// ---------------------------------------------------------------------------
// Scratch (static __device__ arrays: allocation-free, graph-capture safe)
// ---------------------------------------------------------------------------
__device__ float g_value[(size_t)N_B * LIN * CDIM];      // 42.5 MB fp32
__device__ float g_oa[(size_t)N_B * LQ * 128];           // fused offsets(96)+attn(32)
__device__ __half g_samp[(size_t)N_B * LQ * CDIM];       // sampled (fp16)

// pre-transposed fp16 weights: [N][K]
__device__ __half g_wv[CDIM * CDIM];
__device__ __half g_wo[CDIM * CDIM];
__device__ __half g_woa[128 * CDIM];   // rows 0..95 = w_off, 96..127 = w_att

// ---------------------------------------------------------------------------
// PTX helpers (baseline ISA: ldmatrix + mma.sync + cp.async, sm_80+)
// ---------------------------------------------------------------------------
__device__ __forceinline__ uint32_t smem_u32(const void* p) {
    uint32_t a;
    asm("{ .reg .u64 t; cvta.to.shared.u64 t, %1; cvt.u32.u64 %0, t; }" : "=r"(a) : "l"(p));
    return a;
}
__device__ __forceinline__ void ldmx4(uint32_t& r0, uint32_t& r1, uint32_t& r2,
                                      uint32_t& r3, uint32_t addr) {
    asm volatile("ldmatrix.sync.aligned.m8n8.x4.shared.b16 {%0,%1,%2,%3}, [%4];"
                 : "=r"(r0), "=r"(r1), "=r"(r2), "=r"(r3) : "r"(addr));
}
__device__ __forceinline__ void mma16816(float* d, const uint32_t* a, const uint32_t* b) {
    asm volatile(
        "mma.sync.aligned.m16n8k16.row.col.f32.f16.f16.f32 "
        "{%0,%1,%2,%3}, {%4,%5,%6,%7}, {%8,%9}, {%0,%1,%2,%3};"
        : "+f"(d[0]), "+f"(d[1]), "+f"(d[2]), "+f"(d[3])
        : "r"(a[0]), "r"(a[1]), "r"(a[2]), "r"(a[3]), "r"(b[0]), "r"(b[1]));
}
__device__ __forceinline__ void cpasync16(uint32_t dst, const void* src) {
    asm volatile("cp.async.cg.shared.global [%0], [%1], 16;" :: "r"(dst), "l"(src));
}
#define CP_COMMIT() asm volatile("cp.async.commit_group;" ::: "memory")
#define CP_WAIT(n)  asm volatile("cp.async.wait_group %0;" :: "n"(n) : "memory")

__device__ __forceinline__ uint32_t cvt2(float x, float y) {
    __half2 h = __floats2half2_rn(x, y);
    return *reinterpret_cast<uint32_t*>(&h);
}

// ---------------------------------------------------------------------------
// Coalesced tiled transpose + fp16 convert: h[n*K+k] = (half)w[k*N+n]
// grid (K/32, N/32), block (32, 8). K, N multiples of 32.
// ---------------------------------------------------------------------------
__global__ void transpose_h(const float* __restrict__ w, __half* __restrict__ h,
                            int K, int N)
{
    __shared__ float tile[32][33];
    const int k0 = blockIdx.x * 32, n0 = blockIdx.y * 32;
    const int tx = threadIdx.x, ty = threadIdx.y;
    #pragma unroll
    for (int i = 0; i < 32; i += 8)
        tile[ty + i][tx] = w[(size_t)(k0 + ty + i) * N + n0 + tx];
    __syncthreads();
    #pragma unroll
    for (int i = 0; i < 32; i += 8)
        h[(size_t)(n0 + ty + i) * K + k0 + tx] = __float2half(tile[tx][ty + i]);
}

// ---------------------------------------------------------------------------
// fp16 HMMA GEMM: C[M,128] = A[M,K] @ Bt[128,K]^T + bias
// BM=128, BN=128, BK=32, 256 threads = 4(m) x 2(n) warps; warp tile 32x64.
// PRE=false: A fp32, converted inline (LDG->cvt->STS); B via cp.async (2-stage).
// PRE=true : A pre-converted fp16; 4-stage all-cp.async pipeline.
// ---------------------------------------------------------------------------
template <bool PRE>
__global__ void __launch_bounds__(256)
gemm_mma(const float* __restrict__ A32, const __half* __restrict__ Ah,
         const __half* __restrict__ Bt,
         const float* __restrict__ bias, const float* __restrict__ bias2, int nsplit,
         float* __restrict__ C, int M, int N, int K)
{
    constexpr int BM = 128, BN = 128, BK = 32, SA = 40;
    constexpr int WN = BN / 2, NF = WN / 8;        // 8 n-frags per warp
    constexpr int A_ELE = BM * SA;
    constexpr int B_ELE = BN * SA;
    constexpr int BUF = A_ELE + B_ELE;             // fp16 elems per stage
    constexpr int STAGES = PRE ? 4 : 2;

    extern __shared__ __half smbuf[];
    const uint32_t sbase = smem_u32(smbuf);

    const int tid = threadIdx.x;
    const int lane = tid & 31;
    const int wid = tid >> 5;
    const int wm = wid & 3, wn = wid >> 2;
    const int bm = blockIdx.y * BM, bn = blockIdx.x * BN;
    const int nch = K / BK;

    float acc[2][NF][4];
    #pragma unroll
    for (int i = 0; i < 2; i++)
        #pragma unroll
        for (int j = 0; j < NF; j++)
            #pragma unroll
            for (int q = 0; q < 4; q++) acc[i][j][q] = 0.f;

    float4 aR[4];

    auto asyncB = [&](int c, int buf) {
        const int k0 = c * BK;
        const uint32_t base = sbase + (uint32_t)buf * BUF * 2;
        #pragma unroll
        for (int t = 0; t < 2; t++) {
            int l = t * 256 + tid;
            int rr = l >> 2, q = l & 3;
            uint32_t dst = base + (uint32_t)(A_ELE + rr * SA + q * 8) * 2;
            cpasync16(dst, &Bt[(size_t)(bn + rr) * K + k0 + q * 8]);
        }
    };
    auto asyncA = [&](int c, int buf) {    // PRE only
        const int k0 = c * BK;
        const uint32_t base = sbase + (uint32_t)buf * BUF * 2;
        #pragma unroll
        for (int t = 0; t < 2; t++) {
            int l = t * 256 + tid;
            int rr = l >> 2, q = l & 3;
            uint32_t dst = base + (uint32_t)(rr * SA + q * 8) * 2;
            cpasync16(dst, &Ah[(size_t)(bm + rr) * K + k0 + q * 8]);
        }
    };
    auto loadA = [&](int c) {              // !PRE
        const int k0 = c * BK;
        #pragma unroll
        for (int t = 0; t < 4; t++) {
            int l = t * 256 + tid;
            int row = l >> 3, c4 = l & 7;
            aR[t] = *reinterpret_cast<const float4*>(&A32[(size_t)(bm + row) * K + k0 + c4 * 4]);
        }
    };
    auto stsA = [&](int buf) {             // !PRE
        const uint32_t base = sbase + (uint32_t)buf * BUF * 2;
        #pragma unroll
        for (int t = 0; t < 4; t++) {
            int l = t * 256 + tid;
            int row = l >> 3, c4 = l & 7;
            uint32_t a01 = cvt2(aR[t].x, aR[t].y);
            uint32_t a23 = cvt2(aR[t].z, aR[t].w);
            uint32_t off = (uint32_t)(row * SA + c4 * 4) * 2;
            asm volatile("st.shared.v2.b32 [%0], {%1,%2};"
                         :: "r"(base + off), "r"(a01), "r"(a23) : "memory");
        }
    };
    auto compute = [&](int buf) {
        const uint32_t base = sbase + (uint32_t)buf * BUF * 2;
        const uint32_t aS = base;
        const uint32_t bS = base + A_ELE * 2;
        #pragma unroll
        for (int s = 0; s < 2; s++) {
            uint32_t ah[2][4], bh[NF][2];
            #pragma unroll
            for (int i = 0; i < 2; i++) {
                uint32_t row = wm * 32 + i * 16 + (lane & 15);
                uint32_t off = (row * SA + s * 16 + (lane >> 4) * 8) * 2;
                ldmx4(ah[i][0], ah[i][1], ah[i][2], ah[i][3], aS + off);
            }
            #pragma unroll
            for (int j = 0; j < NF; j += 2) {
                uint32_t row = wn * WN + j * 8 + (lane & 7) + ((lane & 16) ? 8 : 0);
                uint32_t off = (row * SA + s * 16 + ((lane >> 3) & 1) * 8) * 2;
                ldmx4(bh[j][0], bh[j][1], bh[j + 1][0], bh[j + 1][1], bS + off);
            }
            #pragma unroll
            for (int i = 0; i < 2; i++)
                #pragma unroll
                for (int j = 0; j < NF; j++)
                    mma16816(acc[i][j], ah[i], bh[j]);
        }
    };

    if constexpr (PRE) {
        #pragma unroll
        for (int i = 0; i < STAGES - 1; i++) {
            asyncA(i, i); asyncB(i, i); CP_COMMIT();
        }
        for (int c = 0; c < nch; c++) {
            CP_WAIT(STAGES - 2);
            __syncthreads();
            int f = c + STAGES - 1;
            if (f < nch) { asyncA(f, f % STAGES); asyncB(f, f % STAGES); }
            CP_COMMIT();                   // empty group in tail keeps wait counts valid
            compute(c % STAGES);
        }
    } else {
        asyncB(0, 0); CP_COMMIT();
        loadA(0);
        CP_WAIT(0);
        stsA(0);
        __syncthreads();
        for (int c = 0; c < nch; c++) {
            if (c + 1 < nch) { asyncB(c + 1, (c + 1) & 1); CP_COMMIT(); loadA(c + 1); }
            compute(c & 1);
            if (c + 1 < nch) { CP_WAIT(0); stsA((c + 1) & 1); }
            __syncthreads();
        }
    }

    // Epilogue: direct float2 stores + (possibly concatenated) bias
    #pragma unroll
    for (int i = 0; i < 2; i++) {
        int r0 = bm + wm * 32 + i * 16 + (lane >> 2);
        #pragma unroll
        for (int j = 0; j < NF; j++) {
            int col = bn + wn * WN + j * 8 + (lane & 3) * 2;
            float b0 = (col < nsplit) ? bias[col] : bias2[col - nsplit];
            float b1 = (col + 1 < nsplit) ? bias[col + 1] : bias2[col + 1 - nsplit];
            float2 v0 = make_float2(acc[i][j][0] + b0, acc[i][j][1] + b1);
            float2 v1 = make_float2(acc[i][j][2] + b0, acc[i][j][3] + b1);
            *reinterpret_cast<float2*>(&C[(size_t)r0 * N + col]) = v0;
            *reinterpret_cast<float2*>(&C[(size_t)(r0 + 8) * N + col]) = v1;
        }
    }
}

// ---------------------------------------------------------------------------
// Sampler: 768 threads = 4 queries x 192 gather threads (float4 = 4 channels).
// Reads fused g_oa (offsets cols 0..95, attn logits 96..127).
// Writes fp16 sampled output for the out-projection GEMM.
// ---------------------------------------------------------------------------
__global__ void __launch_bounds__(768) sample_kernel(const float* __restrict__ refpts)
{
    const int b0 = blockIdx.x * 4;

    __shared__ float s_attn[4][32];
    __shared__ int   s_idx[4][32][8];
    __shared__ float s_w[4][32][8];

    const int tid = threadIdx.x;

    if (tid < 128) {
        int qi = tid >> 5, hp = tid & 31;
        int bq = b0 + qi;
        const float* oa = &g_oa[(size_t)bq * 128 + hp * 3];
        float rx = refpts[(size_t)bq * 3 + 0];
        float ry = refpts[(size_t)bq * 3 + 1];
        float rz = refpts[(size_t)bq * 3 + 2];
        // pixel = 12*(ref + off/12) - 0.5 = 12*ref + off - 0.5
        float x = 12.f * rx + oa[0] - 0.5f;
        float y = 12.f * ry + oa[1] - 0.5f;
        float z = 12.f * rz + oa[2] - 0.5f;
        float x0f = floorf(x), y0f = floorf(y), z0f = floorf(z);
        int x0 = (int)x0f, y0 = (int)y0f, z0 = (int)z0f;
        float fx = x - x0f, fy = y - y0f, fz = z - z0f;
        #pragma unroll
        for (int c = 0; c < 8; c++) {
            int dx = c & 1, dy = (c >> 1) & 1, dz = (c >> 2) & 1;
            int xi = x0 + dx, yi = y0 + dy, zi = z0 + dz;
            float w = (dx ? fx : 1.f - fx) * (dy ? fy : 1.f - fy) * (dz ? fz : 1.f - fz);
            bool valid = (xi >= 0) & (xi < NVOX) & (yi >= 0) & (yi < NVOX) &
                         (zi >= 0) & (zi < NVOX);
            int xc = min(max(xi, 0), NVOX - 1);
            int yc = min(max(yi, 0), NVOX - 1);
            int zc = min(max(zi, 0), NVOX - 1);
            s_idx[qi][hp][c] = (zc * NVOX + yc) * NVOX + xc;
            s_w[qi][hp][c] = valid ? w : 0.f;
        }
    }
    if (tid >= 128 && tid < 160) {
        int idx = tid - 128;
        int qi = idx >> 3, h = idx & 7;
        const float* lg = &g_oa[(size_t)(b0 + qi) * 128 + 96 + h * 4];
        float m = fmaxf(fmaxf(lg[0], lg[1]), fmaxf(lg[2], lg[3]));
        float e0 = expf(lg[0] - m), e1 = expf(lg[1] - m);
        float e2 = expf(lg[2] - m), e3 = expf(lg[3] - m);
        float inv = 1.f / (e0 + e1 + e2 + e3);
        s_attn[qi][h * 4 + 0] = e0 * inv;
        s_attn[qi][h * 4 + 1] = e1 * inv;
        s_attn[qi][h * 4 + 2] = e2 * inv;
        s_attn[qi][h * 4 + 3] = e3 * inv;
    }
    __syncthreads();

    const int qi = tid / 192;
    const int tt = tid % 192;
    const int h = tt / 24;
    const int c4 = (tt % 24) * 4;
    const int bq = b0 + qi;
    const int n = bq >> 12;
    const float* vbase = &g_value[(size_t)n * LIN * CDIM + h * DD + c4];

    float4 acc = make_float4(0.f, 0.f, 0.f, 0.f);
    #pragma unroll
    for (int p = 0; p < PP; p++) {
        int hp = h * PP + p;
        float a = s_attn[qi][hp];
        float4 sv = make_float4(0.f, 0.f, 0.f, 0.f);
        #pragma unroll
        for (int c = 0; c < 8; c++) {
            float w = s_w[qi][hp][c];
            const float4 v = *reinterpret_cast<const float4*>(
                vbase + (size_t)s_idx[qi][hp][c] * CDIM);
            sv.x = fmaf(w, v.x, sv.x);
            sv.y = fmaf(w, v.y, sv.y);
            sv.z = fmaf(w, v.z, sv.z);
            sv.w = fmaf(w, v.w, sv.w);
        }
        acc.x = fmaf(a, sv.x, acc.x);
        acc.y = fmaf(a, sv.y, acc.y);
        acc.z = fmaf(a, sv.z, acc.z);
        acc.w = fmaf(a, sv.w, acc.w);
    }

    uint32_t p01 = cvt2(acc.x, acc.y);
    uint32_t p23 = cvt2(acc.z, acc.w);
    size_t o = (size_t)bq * CDIM + h * DD + c4;
    *reinterpret_cast<uint2*>(&g_samp[o]) = make_uint2(p01, p23);
}

// ---------------------------------------------------------------------------
// Launch
// ---------------------------------------------------------------------------
extern "C" void kernel_launch(void* const* d_in, const int* in_sizes, int n_in,
                              void* d_out, int out_size)
{
    const float* query = (const float*)d_in[0];
    const float* refp  = (const float*)d_in[1];
    const float* inp   = (const float*)d_in[2];
    const float* w_val = (const float*)d_in[3];
    const float* b_val = (const float*)d_in[4];
    const float* w_off = (const float*)d_in[5];
    const float* b_off = (const float*)d_in[6];
    const float* w_att = (const float*)d_in[7];
    const float* b_att = (const float*)d_in[8];
    const float* w_out = (const float*)d_in[9];
    const float* b_out = (const float*)d_in[10];
    float* out = (float*)d_out;

    float *pv, *poa;
    cudaGetSymbolAddress((void**)&pv, g_value);
    cudaGetSymbolAddress((void**)&poa, g_oa);
    __half *sp, *wv, *wo, *woa;
    cudaGetSymbolAddress((void**)&sp, g_samp);
    cudaGetSymbolAddress((void**)&wv, g_wv);
    cudaGetSymbolAddress((void**)&wo, g_wo);
    cudaGetSymbolAddress((void**)&woa, g_woa);

    // dynamic smem: stage = (128+128)*40 halves = 20480 B
    const int SMEM_NP  = 2 * 20480;   // 40 KB (2-stage)
    const int SMEM_PRE = 4 * 20480;   // 80 KB (4-stage)
    cudaFuncSetAttribute(gemm_mma<false>, cudaFuncAttributeMaxDynamicSharedMemorySize, SMEM_NP);
    cudaFuncSetAttribute(gemm_mma<true>,  cudaFuncAttributeMaxDynamicSharedMemorySize, SMEM_PRE);

    const int Mv = N_B * LIN;   // 13824
    const int Mq = N_B * LQ;    // 32768

    // weight transpose + fp16 convert (coalesced tiled)
    transpose_h<<<dim3(CDIM / 32, CDIM / 32), dim3(32, 8)>>>(w_val, wv, CDIM, CDIM);
    transpose_h<<<dim3(CDIM / 32, 96 / 32), dim3(32, 8)>>>(w_off, woa, CDIM, 96);
    transpose_h<<<dim3(CDIM / 32, 32 / 32), dim3(32, 8)>>>(w_att, woa + 96 * CDIM, CDIM, 32);
    transpose_h<<<dim3(CDIM / 32, CDIM / 32), dim3(32, 8)>>>(w_out, wo, CDIM, CDIM);

    // value = input_flatten @ w_val + b_val   (13824 x 768 x 768)
    gemm_mma<false><<<dim3(CDIM / 128, Mv / 128), 256, SMEM_NP>>>(
        inp, nullptr, wv, b_val, b_val, CDIM, pv, Mv, CDIM, CDIM);

    // fused [offsets | attn] = query @ [w_off | w_att] + [b_off | b_att]  (32768 x 128 x 768)
    gemm_mma<false><<<dim3(1, Mq / 128), 256, SMEM_NP>>>(
        query, nullptr, woa, b_off, b_att, 96, poa, Mq, 128, CDIM);

    // softmax + trilinear gather -> fp16 sampled output
    sample_kernel<<<Mq / 4, 768>>>(refp);

    // out = samp @ w_out + b_out              (32768 x 768 x 768), pre-converted A
    gemm_mma<true><<<dim3(CDIM / 128, Mq / 128), 256, SMEM_PRE>>>(
        nullptr, sp, wo, b_out, b_out, CDIM, out, Mq, CDIM, CDIM);
}

// round 6
// speedup vs baseline: 4.8608x; 1.1731x over previous
#include <cuda_runtime.h>
#include <cuda_fp16.h>
#include <math.h>
#include <stdint.h>

// Problem constants
#define N_B 8
#define LQ 4096
#define CDIM 768
#define HH 8
#define PP 4
#define DD 96
#define LIN 1728
#define NVOX 12

// ---------------------------------------------------------------------------
// Scratch (static __device__ arrays: allocation-free, graph-capture safe)
// ---------------------------------------------------------------------------
__device__ __half g_valh[(size_t)N_B * LIN * CDIM];      // value (fp16) 21.2 MB
__device__ float g_oa[(size_t)N_B * LQ * 128];           // fused offsets(96)+attn(32)
__device__ __half g_samp[(size_t)N_B * LQ * CDIM];       // sampled (fp16)

// pre-transposed fp16 weights: [N][K]
__device__ __half g_wv[CDIM * CDIM];
__device__ __half g_wo[CDIM * CDIM];
__device__ __half g_woa[128 * CDIM];   // rows 0..95 = w_off, 96..127 = w_att

// ---------------------------------------------------------------------------
// PTX helpers (baseline ISA: ldmatrix + mma.sync + cp.async, sm_80+)
// ---------------------------------------------------------------------------
__device__ __forceinline__ uint32_t smem_u32(const void* p) {
    uint32_t a;
    asm("{ .reg .u64 t; cvta.to.shared.u64 t, %1; cvt.u32.u64 %0, t; }" : "=r"(a) : "l"(p));
    return a;
}
__device__ __forceinline__ void ldmx4(uint32_t& r0, uint32_t& r1, uint32_t& r2,
                                      uint32_t& r3, uint32_t addr) {
    asm volatile("ldmatrix.sync.aligned.m8n8.x4.shared.b16 {%0,%1,%2,%3}, [%4];"
                 : "=r"(r0), "=r"(r1), "=r"(r2), "=r"(r3) : "r"(addr));
}
__device__ __forceinline__ void mma16816(float* d, const uint32_t* a, const uint32_t* b) {
    asm volatile(
        "mma.sync.aligned.m16n8k16.row.col.f32.f16.f16.f32 "
        "{%0,%1,%2,%3}, {%4,%5,%6,%7}, {%8,%9}, {%0,%1,%2,%3};"
        : "+f"(d[0]), "+f"(d[1]), "+f"(d[2]), "+f"(d[3])
        : "r"(a[0]), "r"(a[1]), "r"(a[2]), "r"(a[3]), "r"(b[0]), "r"(b[1]));
}
__device__ __forceinline__ void cpasync16(uint32_t dst, const void* src) {
    asm volatile("cp.async.cg.shared.global [%0], [%1], 16;" :: "r"(dst), "l"(src));
}
#define CP_COMMIT() asm volatile("cp.async.commit_group;" ::: "memory")
#define CP_WAIT(n)  asm volatile("cp.async.wait_group %0;" :: "n"(n) : "memory")

__device__ __forceinline__ uint32_t cvt2(float x, float y) {
    __half2 h = __floats2half2_rn(x, y);
    return *reinterpret_cast<uint32_t*>(&h);
}

// ---------------------------------------------------------------------------
// Coalesced tiled transpose + fp16 convert: h[n*K+k] = (half)w[k*N+n]
// ---------------------------------------------------------------------------
__global__ void transpose_h(const float* __restrict__ w, __half* __restrict__ h,
                            int K, int N)
{
    __shared__ float tile[32][33];
    const int k0 = blockIdx.x * 32, n0 = blockIdx.y * 32;
    const int tx = threadIdx.x, ty = threadIdx.y;
    #pragma unroll
    for (int i = 0; i < 32; i += 8)
        tile[ty + i][tx] = w[(size_t)(k0 + ty + i) * N + n0 + tx];
    __syncthreads();
    #pragma unroll
    for (int i = 0; i < 32; i += 8)
        h[(size_t)(n0 + ty + i) * K + k0 + tx] = __float2half(tile[tx][ty + i]);
}

// ---------------------------------------------------------------------------
// fp16 HMMA GEMM: C[M,128] = A[M,K] @ Bt[128,K]^T + bias
// BM=128, BN=128, BK=32, 256 threads = 4(m) x 2(n) warps; warp tile 32x64.
// PRE=false: A fp32, converted inline; B via cp.async (2-stage).
// PRE=true : A pre-converted fp16; 4-stage all-cp.async pipeline.
// OUTH:     write fp16 output instead of fp32.
// ---------------------------------------------------------------------------
template <bool PRE, bool OUTH>
__global__ void __launch_bounds__(256)
gemm_mma(const float* __restrict__ A32, const __half* __restrict__ Ah,
         const __half* __restrict__ Bt,
         const float* __restrict__ bias, const float* __restrict__ bias2, int nsplit,
         void* __restrict__ Cout, int M, int N, int K)
{
    constexpr int BM = 128, BN = 128, BK = 32, SA = 40;
    constexpr int WN = BN / 2, NF = WN / 8;
    constexpr int A_ELE = BM * SA;
    constexpr int B_ELE = BN * SA;
    constexpr int BUF = A_ELE + B_ELE;
    constexpr int STAGES = PRE ? 4 : 2;

    extern __shared__ __half smbuf[];
    const uint32_t sbase = smem_u32(smbuf);

    const int tid = threadIdx.x;
    const int lane = tid & 31;
    const int wid = tid >> 5;
    const int wm = wid & 3, wn = wid >> 2;
    const int bm = blockIdx.y * BM, bn = blockIdx.x * BN;
    const int nch = K / BK;

    float acc[2][NF][4];
    #pragma unroll
    for (int i = 0; i < 2; i++)
        #pragma unroll
        for (int j = 0; j < NF; j++)
            #pragma unroll
            for (int q = 0; q < 4; q++) acc[i][j][q] = 0.f;

    float4 aR[4];

    auto asyncB = [&](int c, int buf) {
        const int k0 = c * BK;
        const uint32_t base = sbase + (uint32_t)buf * BUF * 2;
        #pragma unroll
        for (int t = 0; t < 2; t++) {
            int l = t * 256 + tid;
            int rr = l >> 2, q = l & 3;
            uint32_t dst = base + (uint32_t)(A_ELE + rr * SA + q * 8) * 2;
            cpasync16(dst, &Bt[(size_t)(bn + rr) * K + k0 + q * 8]);
        }
    };
    auto asyncA = [&](int c, int buf) {    // PRE only
        const int k0 = c * BK;
        const uint32_t base = sbase + (uint32_t)buf * BUF * 2;
        #pragma unroll
        for (int t = 0; t < 2; t++) {
            int l = t * 256 + tid;
            int rr = l >> 2, q = l & 3;
            uint32_t dst = base + (uint32_t)(rr * SA + q * 8) * 2;
            cpasync16(dst, &Ah[(size_t)(bm + rr) * K + k0 + q * 8]);
        }
    };
    auto loadA = [&](int c) {              // !PRE
        const int k0 = c * BK;
        #pragma unroll
        for (int t = 0; t < 4; t++) {
            int l = t * 256 + tid;
            int row = l >> 3, c4 = l & 7;
            aR[t] = *reinterpret_cast<const float4*>(&A32[(size_t)(bm + row) * K + k0 + c4 * 4]);
        }
    };
    auto stsA = [&](int buf) {             // !PRE
        const uint32_t base = sbase + (uint32_t)buf * BUF * 2;
        #pragma unroll
        for (int t = 0; t < 4; t++) {
            int l = t * 256 + tid;
            int row = l >> 3, c4 = l & 7;
            uint32_t a01 = cvt2(aR[t].x, aR[t].y);
            uint32_t a23 = cvt2(aR[t].z, aR[t].w);
            uint32_t off = (uint32_t)(row * SA + c4 * 4) * 2;
            asm volatile("st.shared.v2.b32 [%0], {%1,%2};"
                         :: "r"(base + off), "r"(a01), "r"(a23) : "memory");
        }
    };
    auto compute = [&](int buf) {
        const uint32_t base = sbase + (uint32_t)buf * BUF * 2;
        const uint32_t aS = base;
        const uint32_t bS = base + A_ELE * 2;
        #pragma unroll
        for (int s = 0; s < 2; s++) {
            uint32_t ah[2][4], bh[NF][2];
            #pragma unroll
            for (int i = 0; i < 2; i++) {
                uint32_t row = wm * 32 + i * 16 + (lane & 15);
                uint32_t off = (row * SA + s * 16 + (lane >> 4) * 8) * 2;
                ldmx4(ah[i][0], ah[i][1], ah[i][2], ah[i][3], aS + off);
            }
            #pragma unroll
            for (int j = 0; j < NF; j += 2) {
                uint32_t row = wn * WN + j * 8 + (lane & 7) + ((lane & 16) ? 8 : 0);
                uint32_t off = (row * SA + s * 16 + ((lane >> 3) & 1) * 8) * 2;
                ldmx4(bh[j][0], bh[j][1], bh[j + 1][0], bh[j + 1][1], bS + off);
            }
            #pragma unroll
            for (int i = 0; i < 2; i++)
                #pragma unroll
                for (int j = 0; j < NF; j++)
                    mma16816(acc[i][j], ah[i], bh[j]);
        }
    };

    if constexpr (PRE) {
        #pragma unroll
        for (int i = 0; i < STAGES - 1; i++) {
            asyncA(i, i); asyncB(i, i); CP_COMMIT();
        }
        for (int c = 0; c < nch; c++) {
            CP_WAIT(STAGES - 2);
            __syncthreads();
            int f = c + STAGES - 1;
            if (f < nch) { asyncA(f, f % STAGES); asyncB(f, f % STAGES); }
            CP_COMMIT();
            compute(c % STAGES);
        }
    } else {
        asyncB(0, 0); CP_COMMIT();
        loadA(0);
        CP_WAIT(0);
        stsA(0);
        __syncthreads();
        for (int c = 0; c < nch; c++) {
            if (c + 1 < nch) { asyncB(c + 1, (c + 1) & 1); CP_COMMIT(); loadA(c + 1); }
            compute(c & 1);
            if (c + 1 < nch) { CP_WAIT(0); stsA((c + 1) & 1); }
            __syncthreads();
        }
    }

    // Epilogue: bias add, store fp32 or fp16
    #pragma unroll
    for (int i = 0; i < 2; i++) {
        int r0 = bm + wm * 32 + i * 16 + (lane >> 2);
        #pragma unroll
        for (int j = 0; j < NF; j++) {
            int col = bn + wn * WN + j * 8 + (lane & 3) * 2;
            float b0 = (col < nsplit) ? bias[col] : bias2[col - nsplit];
            float b1 = (col + 1 < nsplit) ? bias[col + 1] : bias2[col + 1 - nsplit];
            if constexpr (OUTH) {
                __half* C = (__half*)Cout;
                uint32_t v0 = cvt2(acc[i][j][0] + b0, acc[i][j][1] + b1);
                uint32_t v1 = cvt2(acc[i][j][2] + b0, acc[i][j][3] + b1);
                *reinterpret_cast<uint32_t*>(&C[(size_t)r0 * N + col]) = v0;
                *reinterpret_cast<uint32_t*>(&C[(size_t)(r0 + 8) * N + col]) = v1;
            } else {
                float* C = (float*)Cout;
                float2 v0 = make_float2(acc[i][j][0] + b0, acc[i][j][1] + b1);
                float2 v1 = make_float2(acc[i][j][2] + b0, acc[i][j][3] + b1);
                *reinterpret_cast<float2*>(&C[(size_t)r0 * N + col]) = v0;
                *reinterpret_cast<float2*>(&C[(size_t)(r0 + 8) * N + col]) = v1;
            }
        }
    }
}

// ---------------------------------------------------------------------------
// Sampler: 768 threads = 8 queries x 96 gather threads (uint4 = 8 fp16 ch).
// Reads fp16 value; fp32 accumulation; writes fp16 sampled output.
// ---------------------------------------------------------------------------
__global__ void __launch_bounds__(768) sample_kernel(const float* __restrict__ refpts)
{
    const int b0 = blockIdx.x * 8;

    __shared__ float s_attn[8][32];
    __shared__ int   s_idx[8][32][8];
    __shared__ float s_w[8][32][8];

    const int tid = threadIdx.x;

    if (tid < 256) {
        int qi = tid >> 5, hp = tid & 31;
        int bq = b0 + qi;
        const float* oa = &g_oa[(size_t)bq * 128 + hp * 3];
        float rx = refpts[(size_t)bq * 3 + 0];
        float ry = refpts[(size_t)bq * 3 + 1];
        float rz = refpts[(size_t)bq * 3 + 2];
        // pixel = 12*ref + off - 0.5
        float x = 12.f * rx + oa[0] - 0.5f;
        float y = 12.f * ry + oa[1] - 0.5f;
        float z = 12.f * rz + oa[2] - 0.5f;
        float x0f = floorf(x), y0f = floorf(y), z0f = floorf(z);
        int x0 = (int)x0f, y0 = (int)y0f, z0 = (int)z0f;
        float fx = x - x0f, fy = y - y0f, fz = z - z0f;
        #pragma unroll
        for (int c = 0; c < 8; c++) {
            int dx = c & 1, dy = (c >> 1) & 1, dz = (c >> 2) & 1;
            int xi = x0 + dx, yi = y0 + dy, zi = z0 + dz;
            float w = (dx ? fx : 1.f - fx) * (dy ? fy : 1.f - fy) * (dz ? fz : 1.f - fz);
            bool valid = (xi >= 0) & (xi < NVOX) & (yi >= 0) & (yi < NVOX) &
                         (zi >= 0) & (zi < NVOX);
            int xc = min(max(xi, 0), NVOX - 1);
            int yc = min(max(yi, 0), NVOX - 1);
            int zc = min(max(zi, 0), NVOX - 1);
            s_idx[qi][hp][c] = (zc * NVOX + yc) * NVOX + xc;
            s_w[qi][hp][c] = valid ? w : 0.f;
        }
    }
    if (tid >= 256 && tid < 320) {
        int idx = tid - 256;
        int qi = idx >> 3, h = idx & 7;
        const float* lg = &g_oa[(size_t)(b0 + qi) * 128 + 96 + h * 4];
        float m = fmaxf(fmaxf(lg[0], lg[1]), fmaxf(lg[2], lg[3]));
        float e0 = expf(lg[0] - m), e1 = expf(lg[1] - m);
        float e2 = expf(lg[2] - m), e3 = expf(lg[3] - m);
        float inv = 1.f / (e0 + e1 + e2 + e3);
        s_attn[qi][h * 4 + 0] = e0 * inv;
        s_attn[qi][h * 4 + 1] = e1 * inv;
        s_attn[qi][h * 4 + 2] = e2 * inv;
        s_attn[qi][h * 4 + 3] = e3 * inv;
    }
    __syncthreads();

    const int qi = tid / 96;
    const int tt = tid % 96;
    const int h = tt / 12;
    const int c8 = (tt % 12) * 8;
    const int bq = b0 + qi;
    const int n = bq >> 12;
    const __half* vbase = &g_valh[(size_t)n * LIN * CDIM + h * DD + c8];

    float acc[8];
    #pragma unroll
    for (int k = 0; k < 8; k++) acc[k] = 0.f;

    #pragma unroll
    for (int p = 0; p < PP; p++) {
        int hp = h * PP + p;
        float a = s_attn[qi][hp];
        float sv[8];
        #pragma unroll
        for (int k = 0; k < 8; k++) sv[k] = 0.f;
        #pragma unroll
        for (int c = 0; c < 8; c++) {
            float w = s_w[qi][hp][c];
            uint4 v = *reinterpret_cast<const uint4*>(
                vbase + (size_t)s_idx[qi][hp][c] * CDIM);
            const __half2* hv = reinterpret_cast<const __half2*>(&v);
            #pragma unroll
            for (int k = 0; k < 4; k++) {
                float2 f = __half22float2(hv[k]);
                sv[2 * k]     = fmaf(w, f.x, sv[2 * k]);
                sv[2 * k + 1] = fmaf(w, f.y, sv[2 * k + 1]);
            }
        }
        #pragma unroll
        for (int k = 0; k < 8; k++) acc[k] = fmaf(a, sv[k], acc[k]);
    }

    uint4 o;
    o.x = cvt2(acc[0], acc[1]);
    o.y = cvt2(acc[2], acc[3]);
    o.z = cvt2(acc[4], acc[5]);
    o.w = cvt2(acc[6], acc[7]);
    *reinterpret_cast<uint4*>(&g_samp[(size_t)bq * CDIM + h * DD + c8]) = o;
}

// ---------------------------------------------------------------------------
// Launch
// ---------------------------------------------------------------------------
extern "C" void kernel_launch(void* const* d_in, const int* in_sizes, int n_in,
                              void* d_out, int out_size)
{
    const float* query = (const float*)d_in[0];
    const float* refp  = (const float*)d_in[1];
    const float* inp   = (const float*)d_in[2];
    const float* w_val = (const float*)d_in[3];
    const float* b_val = (const float*)d_in[4];
    const float* w_off = (const float*)d_in[5];
    const float* b_off = (const float*)d_in[6];
    const float* w_att = (const float*)d_in[7];
    const float* b_att = (const float*)d_in[8];
    const float* w_out = (const float*)d_in[9];
    const float* b_out = (const float*)d_in[10];
    float* out = (float*)d_out;

    float* poa;
    cudaGetSymbolAddress((void**)&poa, g_oa);
    __half *pvh, *sp, *wv, *wo, *woa;
    cudaGetSymbolAddress((void**)&pvh, g_valh);
    cudaGetSymbolAddress((void**)&sp, g_samp);
    cudaGetSymbolAddress((void**)&wv, g_wv);
    cudaGetSymbolAddress((void**)&wo, g_wo);
    cudaGetSymbolAddress((void**)&woa, g_woa);

    const int SMEM_NP  = 2 * 20480;   // 40 KB (2-stage)
    const int SMEM_PRE = 4 * 20480;   // 80 KB (4-stage)
    cudaFuncSetAttribute((const void*)gemm_mma<false, true>,
                         cudaFuncAttributeMaxDynamicSharedMemorySize, SMEM_NP);
    cudaFuncSetAttribute((const void*)gemm_mma<false, false>,
                         cudaFuncAttributeMaxDynamicSharedMemorySize, SMEM_NP);
    cudaFuncSetAttribute((const void*)gemm_mma<true, false>,
                         cudaFuncAttributeMaxDynamicSharedMemorySize, SMEM_PRE);

    const int Mv = N_B * LIN;   // 13824
    const int Mq = N_B * LQ;    // 32768

    // weight transpose + fp16 convert
    transpose_h<<<dim3(CDIM / 32, CDIM / 32), dim3(32, 8)>>>(w_val, wv, CDIM, CDIM);
    transpose_h<<<dim3(CDIM / 32, 96 / 32), dim3(32, 8)>>>(w_off, woa, CDIM, 96);
    transpose_h<<<dim3(CDIM / 32, 32 / 32), dim3(32, 8)>>>(w_att, woa + 96 * CDIM, CDIM, 32);
    transpose_h<<<dim3(CDIM / 32, CDIM / 32), dim3(32, 8)>>>(w_out, wo, CDIM, CDIM);

    // value = input_flatten @ w_val + b_val   (13824 x 768 x 768) -> fp16
    gemm_mma<false, true><<<dim3(CDIM / 128, Mv / 128), 256, SMEM_NP>>>(
        inp, nullptr, wv, b_val, b_val, CDIM, pvh, Mv, CDIM, CDIM);

    // fused [offsets | attn] = query @ [w_off | w_att] + biases  (32768 x 128 x 768)
    gemm_mma<false, false><<<dim3(1, Mq / 128), 256, SMEM_NP>>>(
        query, nullptr, woa, b_off, b_att, 96, poa, Mq, 128, CDIM);

    // softmax + trilinear gather (fp16 value) -> fp16 sampled output
    sample_kernel<<<Mq / 8, 768>>>(refp);

    // out = samp @ w_out + b_out              (32768 x 768 x 768), fp32 out
    gemm_mma<true, false><<<dim3(CDIM / 128, Mq / 128), 256, SMEM_PRE>>>(
        nullptr, sp, wo, b_out, b_out, CDIM, out, Mq, CDIM, CDIM);
}

// round 7
// speedup vs baseline: 4.9964x; 1.0279x over previous
#include <cuda_runtime.h>
#include <cuda_fp16.h>
#include <math.h>
#include <stdint.h>

// Problem constants
#define N_B 8
#define LQ 4096
#define CDIM 768
#define HH 8
#define PP 4
#define DD 96
#define LIN 1728
#define NVOX 12

// ---------------------------------------------------------------------------
// Scratch (static __device__ arrays: allocation-free, graph-capture safe)
// ---------------------------------------------------------------------------
__device__ __half g_valh[(size_t)N_B * LIN * CDIM];      // value (fp16) 21.2 MB
__device__ float g_oa[(size_t)N_B * LQ * 128];           // fused offsets(96)+attn(32)
__device__ __half g_samp[(size_t)N_B * LQ * CDIM];       // sampled (fp16)

// pre-transposed fp16 weights: [N][K]
__device__ __half g_wv[CDIM * CDIM];
__device__ __half g_wo[CDIM * CDIM];
__device__ __half g_woa[128 * CDIM];   // rows 0..95 = w_off, 96..127 = w_att

// ---------------------------------------------------------------------------
// PTX helpers (baseline ISA: ldmatrix + mma.sync + cp.async, sm_80+)
// ---------------------------------------------------------------------------
__device__ __forceinline__ uint32_t smem_u32(const void* p) {
    uint32_t a;
    asm("{ .reg .u64 t; cvta.to.shared.u64 t, %1; cvt.u32.u64 %0, t; }" : "=r"(a) : "l"(p));
    return a;
}
__device__ __forceinline__ void ldmx4(uint32_t& r0, uint32_t& r1, uint32_t& r2,
                                      uint32_t& r3, uint32_t addr) {
    asm volatile("ldmatrix.sync.aligned.m8n8.x4.shared.b16 {%0,%1,%2,%3}, [%4];"
                 : "=r"(r0), "=r"(r1), "=r"(r2), "=r"(r3) : "r"(addr));
}
__device__ __forceinline__ void mma16816(float* d, const uint32_t* a, const uint32_t* b) {
    asm volatile(
        "mma.sync.aligned.m16n8k16.row.col.f32.f16.f16.f32 "
        "{%0,%1,%2,%3}, {%4,%5,%6,%7}, {%8,%9}, {%0,%1,%2,%3};"
        : "+f"(d[0]), "+f"(d[1]), "+f"(d[2]), "+f"(d[3])
        : "r"(a[0]), "r"(a[1]), "r"(a[2]), "r"(a[3]), "r"(b[0]), "r"(b[1]));
}
__device__ __forceinline__ void cpasync16(uint32_t dst, const void* src) {
    asm volatile("cp.async.cg.shared.global [%0], [%1], 16;" :: "r"(dst), "l"(src));
}
#define CP_COMMIT() asm volatile("cp.async.commit_group;" ::: "memory")
#define CP_WAIT(n)  asm volatile("cp.async.wait_group %0;" :: "n"(n) : "memory")

__device__ __forceinline__ uint32_t cvt2(float x, float y) {
    __half2 h = __floats2half2_rn(x, y);
    return *reinterpret_cast<uint32_t*>(&h);
}

// ---------------------------------------------------------------------------
// Coalesced tiled transpose + fp16 convert: h[n*K+k] = (half)w[k*N+n]
// ---------------------------------------------------------------------------
__device__ __forceinline__ void transpose_body(const float* __restrict__ w,
                                               __half* __restrict__ h, int K, int N)
{
    __shared__ float tile[32][33];
    const int k0 = blockIdx.x * 32, n0 = blockIdx.y * 32;
    const int tx = threadIdx.x, ty = threadIdx.y;
    #pragma unroll
    for (int i = 0; i < 32; i += 8)
        tile[ty + i][tx] = w[(size_t)(k0 + ty + i) * N + n0 + tx];
    __syncthreads();
    #pragma unroll
    for (int i = 0; i < 32; i += 8)
        h[(size_t)(n0 + ty + i) * K + k0 + tx] = __float2half(tile[tx][ty + i]);
}
__global__ void transpose_h(const float* __restrict__ w, __half* __restrict__ h,
                            int K, int N)
{
    transpose_body(w, h, K, N);
}
// two 768x768 transposes in one launch (z selects)
__global__ void transpose_h2(const float* __restrict__ w0, __half* __restrict__ h0,
                             const float* __restrict__ w1, __half* __restrict__ h1)
{
    transpose_body(blockIdx.z ? w1 : w0, blockIdx.z ? h1 : h0, CDIM, CDIM);
}

// ---------------------------------------------------------------------------
// fp16 HMMA GEMM: C[M,N-tile] = A[M,K] @ Bt[N,K]^T + bias
// BM=128, BN=128, BK=32; 128 threads = 2(m) x 2(n) warps; warp tile 64x64.
// PRE=false: A fp32, converted inline; B via cp.async (2-stage).
// PRE=true : A pre-converted fp16; 4-stage all-cp.async pipeline.
// OUTH:     write fp16 output instead of fp32.
// ---------------------------------------------------------------------------
template <bool PRE, bool OUTH>
__global__ void __launch_bounds__(128)
gemm_mma(const float* __restrict__ A32, const __half* __restrict__ Ah,
         const __half* __restrict__ Bt,
         const float* __restrict__ bias, const float* __restrict__ bias2, int nsplit,
         void* __restrict__ Cout, int M, int N, int K)
{
    constexpr int BM = 128, BN = 128, BK = 32, SA = 40;
    constexpr int A_ELE = BM * SA;
    constexpr int B_ELE = BN * SA;
    constexpr int BUF = A_ELE + B_ELE;
    constexpr int STAGES = PRE ? 4 : 2;

    extern __shared__ __half smbuf[];
    const uint32_t sbase = smem_u32(smbuf);

    const int tid = threadIdx.x;
    const int lane = tid & 31;
    const int wid = tid >> 5;
    const int wm = wid & 1, wn = wid >> 1;
    const int bm = blockIdx.y * BM, bn = blockIdx.x * BN;
    const int nch = K / BK;

    float acc[4][8][4];
    #pragma unroll
    for (int i = 0; i < 4; i++)
        #pragma unroll
        for (int j = 0; j < 8; j++)
            #pragma unroll
            for (int q = 0; q < 4; q++) acc[i][j][q] = 0.f;

    float4 aR[8];

    auto asyncB = [&](int c, int buf) {
        const int k0 = c * BK;
        const uint32_t base = sbase + (uint32_t)buf * BUF * 2;
        #pragma unroll
        for (int t = 0; t < 4; t++) {
            int l = t * 128 + tid;
            int rr = l >> 2, q = l & 3;
            uint32_t dst = base + (uint32_t)(A_ELE + rr * SA + q * 8) * 2;
            cpasync16(dst, &Bt[(size_t)(bn + rr) * K + k0 + q * 8]);
        }
    };
    auto asyncA = [&](int c, int buf) {    // PRE only
        const int k0 = c * BK;
        const uint32_t base = sbase + (uint32_t)buf * BUF * 2;
        #pragma unroll
        for (int t = 0; t < 4; t++) {
            int l = t * 128 + tid;
            int rr = l >> 2, q = l & 3;
            uint32_t dst = base + (uint32_t)(rr * SA + q * 8) * 2;
            cpasync16(dst, &Ah[(size_t)(bm + rr) * K + k0 + q * 8]);
        }
    };
    auto loadA = [&](int c) {              // !PRE
        const int k0 = c * BK;
        #pragma unroll
        for (int t = 0; t < 8; t++) {
            int l = t * 128 + tid;
            int row = l >> 3, c4 = l & 7;
            aR[t] = *reinterpret_cast<const float4*>(&A32[(size_t)(bm + row) * K + k0 + c4 * 4]);
        }
    };
    auto stsA = [&](int buf) {             // !PRE
        const uint32_t base = sbase + (uint32_t)buf * BUF * 2;
        #pragma unroll
        for (int t = 0; t < 8; t++) {
            int l = t * 128 + tid;
            int row = l >> 3, c4 = l & 7;
            uint32_t a01 = cvt2(aR[t].x, aR[t].y);
            uint32_t a23 = cvt2(aR[t].z, aR[t].w);
            uint32_t off = (uint32_t)(row * SA + c4 * 4) * 2;
            asm volatile("st.shared.v2.b32 [%0], {%1,%2};"
                         :: "r"(base + off), "r"(a01), "r"(a23) : "memory");
        }
    };
    auto compute = [&](int buf) {
        const uint32_t base = sbase + (uint32_t)buf * BUF * 2;
        const uint32_t aS = base;
        const uint32_t bS = base + A_ELE * 2;
        #pragma unroll
        for (int s = 0; s < 2; s++) {
            uint32_t ah[4][4], bh[8][2];
            #pragma unroll
            for (int i = 0; i < 4; i++) {
                uint32_t row = wm * 64 + i * 16 + (lane & 15);
                uint32_t off = (row * SA + s * 16 + (lane >> 4) * 8) * 2;
                ldmx4(ah[i][0], ah[i][1], ah[i][2], ah[i][3], aS + off);
            }
            #pragma unroll
            for (int j = 0; j < 8; j += 2) {
                uint32_t row = wn * 64 + j * 8 + (lane & 7) + ((lane & 16) ? 8 : 0);
                uint32_t off = (row * SA + s * 16 + ((lane >> 3) & 1) * 8) * 2;
                ldmx4(bh[j][0], bh[j][1], bh[j + 1][0], bh[j + 1][1], bS + off);
            }
            #pragma unroll
            for (int i = 0; i < 4; i++)
                #pragma unroll
                for (int j = 0; j < 8; j++)
                    mma16816(acc[i][j], ah[i], bh[j]);
        }
    };

    if constexpr (PRE) {
        #pragma unroll
        for (int i = 0; i < STAGES - 1; i++) {
            asyncA(i, i); asyncB(i, i); CP_COMMIT();
        }
        for (int c = 0; c < nch; c++) {
            CP_WAIT(STAGES - 2);
            __syncthreads();
            int f = c + STAGES - 1;
            if (f < nch) { asyncA(f, f % STAGES); asyncB(f, f % STAGES); }
            CP_COMMIT();
            compute(c % STAGES);
        }
    } else {
        asyncB(0, 0); CP_COMMIT();
        loadA(0);
        CP_WAIT(0);
        stsA(0);
        __syncthreads();
        for (int c = 0; c < nch; c++) {
            if (c + 1 < nch) { asyncB(c + 1, (c + 1) & 1); CP_COMMIT(); loadA(c + 1); }
            compute(c & 1);
            if (c + 1 < nch) { CP_WAIT(0); stsA((c + 1) & 1); }
            __syncthreads();
        }
    }

    // Epilogue: bias add, store fp32 or fp16
    #pragma unroll
    for (int i = 0; i < 4; i++) {
        int r0 = bm + wm * 64 + i * 16 + (lane >> 2);
        #pragma unroll
        for (int j = 0; j < 8; j++) {
            int col = bn + wn * 64 + j * 8 + (lane & 3) * 2;
            float b0 = (col < nsplit) ? bias[col] : bias2[col - nsplit];
            float b1 = (col + 1 < nsplit) ? bias[col + 1] : bias2[col + 1 - nsplit];
            if constexpr (OUTH) {
                __half* C = (__half*)Cout;
                uint32_t v0 = cvt2(acc[i][j][0] + b0, acc[i][j][1] + b1);
                uint32_t v1 = cvt2(acc[i][j][2] + b0, acc[i][j][3] + b1);
                *reinterpret_cast<uint32_t*>(&C[(size_t)r0 * N + col]) = v0;
                *reinterpret_cast<uint32_t*>(&C[(size_t)(r0 + 8) * N + col]) = v1;
            } else {
                float* C = (float*)Cout;
                float2 v0 = make_float2(acc[i][j][0] + b0, acc[i][j][1] + b1);
                float2 v1 = make_float2(acc[i][j][2] + b0, acc[i][j][3] + b1);
                *reinterpret_cast<float2*>(&C[(size_t)r0 * N + col]) = v0;
                *reinterpret_cast<float2*>(&C[(size_t)(r0 + 8) * N + col]) = v1;
            }
        }
    }
}

// ---------------------------------------------------------------------------
// Sampler: 768 threads = 8 queries x 96 gather threads (uint4 = 8 fp16 ch).
// Reads fp16 value; fp32 accumulation; writes fp16 sampled output.
// ---------------------------------------------------------------------------
__global__ void __launch_bounds__(768) sample_kernel(const float* __restrict__ refpts)
{
    const int b0 = blockIdx.x * 8;

    __shared__ float s_attn[8][32];
    __shared__ int   s_idx[8][32][8];
    __shared__ float s_w[8][32][8];

    const int tid = threadIdx.x;

    if (tid < 256) {
        int qi = tid >> 5, hp = tid & 31;
        int bq = b0 + qi;
        const float* oa = &g_oa[(size_t)bq * 128 + hp * 3];
        float rx = refpts[(size_t)bq * 3 + 0];
        float ry = refpts[(size_t)bq * 3 + 1];
        float rz = refpts[(size_t)bq * 3 + 2];
        float x = 12.f * rx + oa[0] - 0.5f;
        float y = 12.f * ry + oa[1] - 0.5f;
        float z = 12.f * rz + oa[2] - 0.5f;
        float x0f = floorf(x), y0f = floorf(y), z0f = floorf(z);
        int x0 = (int)x0f, y0 = (int)y0f, z0 = (int)z0f;
        float fx = x - x0f, fy = y - y0f, fz = z - z0f;
        #pragma unroll
        for (int c = 0; c < 8; c++) {
            int dx = c & 1, dy = (c >> 1) & 1, dz = (c >> 2) & 1;
            int xi = x0 + dx, yi = y0 + dy, zi = z0 + dz;
            float w = (dx ? fx : 1.f - fx) * (dy ? fy : 1.f - fy) * (dz ? fz : 1.f - fz);
            bool valid = (xi >= 0) & (xi < NVOX) & (yi >= 0) & (yi < NVOX) &
                         (zi >= 0) & (zi < NVOX);
            int xc = min(max(xi, 0), NVOX - 1);
            int yc = min(max(yi, 0), NVOX - 1);
            int zc = min(max(zi, 0), NVOX - 1);
            s_idx[qi][hp][c] = (zc * NVOX + yc) * NVOX + xc;
            s_w[qi][hp][c] = valid ? w : 0.f;
        }
    }
    if (tid >= 256 && tid < 320) {
        int idx = tid - 256;
        int qi = idx >> 3, h = idx & 7;
        const float* lg = &g_oa[(size_t)(b0 + qi) * 128 + 96 + h * 4];
        float m = fmaxf(fmaxf(lg[0], lg[1]), fmaxf(lg[2], lg[3]));
        float e0 = expf(lg[0] - m), e1 = expf(lg[1] - m);
        float e2 = expf(lg[2] - m), e3 = expf(lg[3] - m);
        float inv = 1.f / (e0 + e1 + e2 + e3);
        s_attn[qi][h * 4 + 0] = e0 * inv;
        s_attn[qi][h * 4 + 1] = e1 * inv;
        s_attn[qi][h * 4 + 2] = e2 * inv;
        s_attn[qi][h * 4 + 3] = e3 * inv;
    }
    __syncthreads();

    const int qi = tid / 96;
    const int tt = tid % 96;
    const int h = tt / 12;
    const int c8 = (tt % 12) * 8;
    const int bq = b0 + qi;
    const int n = bq >> 12;
    const __half* vbase = &g_valh[(size_t)n * LIN * CDIM + h * DD + c8];

    float acc[8];
    #pragma unroll
    for (int k = 0; k < 8; k++) acc[k] = 0.f;

    #pragma unroll
    for (int p = 0; p < PP; p++) {
        int hp = h * PP + p;
        float a = s_attn[qi][hp];
        float sv[8];
        #pragma unroll
        for (int k = 0; k < 8; k++) sv[k] = 0.f;
        #pragma unroll
        for (int c = 0; c < 8; c++) {
            float w = s_w[qi][hp][c];
            uint4 v = *reinterpret_cast<const uint4*>(
                vbase + (size_t)s_idx[qi][hp][c] * CDIM);
            const __half2* hv = reinterpret_cast<const __half2*>(&v);
            #pragma unroll
            for (int k = 0; k < 4; k++) {
                float2 f = __half22float2(hv[k]);
                sv[2 * k]     = fmaf(w, f.x, sv[2 * k]);
                sv[2 * k + 1] = fmaf(w, f.y, sv[2 * k + 1]);
            }
        }
        #pragma unroll
        for (int k = 0; k < 8; k++) acc[k] = fmaf(a, sv[k], acc[k]);
    }

    uint4 o;
    o.x = cvt2(acc[0], acc[1]);
    o.y = cvt2(acc[2], acc[3]);
    o.z = cvt2(acc[4], acc[5]);
    o.w = cvt2(acc[6], acc[7]);
    *reinterpret_cast<uint4*>(&g_samp[(size_t)bq * CDIM + h * DD + c8]) = o;
}

// ---------------------------------------------------------------------------
// Launch
// ---------------------------------------------------------------------------
extern "C" void kernel_launch(void* const* d_in, const int* in_sizes, int n_in,
                              void* d_out, int out_size)
{
    const float* query = (const float*)d_in[0];
    const float* refp  = (const float*)d_in[1];
    const float* inp   = (const float*)d_in[2];
    const float* w_val = (const float*)d_in[3];
    const float* b_val = (const float*)d_in[4];
    const float* w_off = (const float*)d_in[5];
    const float* b_off = (const float*)d_in[6];
    const float* w_att = (const float*)d_in[7];
    const float* b_att = (const float*)d_in[8];
    const float* w_out = (const float*)d_in[9];
    const float* b_out = (const float*)d_in[10];
    float* out = (float*)d_out;

    float* poa;
    cudaGetSymbolAddress((void**)&poa, g_oa);
    __half *pvh, *sp, *wv, *wo, *woa;
    cudaGetSymbolAddress((void**)&pvh, g_valh);
    cudaGetSymbolAddress((void**)&sp, g_samp);
    cudaGetSymbolAddress((void**)&wv, g_wv);
    cudaGetSymbolAddress((void**)&wo, g_wo);
    cudaGetSymbolAddress((void**)&woa, g_woa);

    const int SMEM_NP  = 2 * 20480;   // 40 KB (2-stage)
    const int SMEM_PRE = 4 * 20480;   // 80 KB (4-stage)
    cudaFuncSetAttribute((const void*)gemm_mma<false, true>,
                         cudaFuncAttributeMaxDynamicSharedMemorySize, SMEM_NP);
    cudaFuncSetAttribute((const void*)gemm_mma<false, false>,
                         cudaFuncAttributeMaxDynamicSharedMemorySize, SMEM_NP);
    cudaFuncSetAttribute((const void*)gemm_mma<true, false>,
                         cudaFuncAttributeMaxDynamicSharedMemorySize, SMEM_PRE);

    const int Mv = N_B * LIN;   // 13824
    const int Mq = N_B * LQ;    // 32768

    // weight transpose + fp16 convert (wv + wo fused into one launch)
    transpose_h2<<<dim3(CDIM / 32, CDIM / 32, 2), dim3(32, 8)>>>(w_val, wv, w_out, wo);
    transpose_h<<<dim3(CDIM / 32, 96 / 32), dim3(32, 8)>>>(w_off, woa, CDIM, 96);
    transpose_h<<<dim3(CDIM / 32, 32 / 32), dim3(32, 8)>>>(w_att, woa + 96 * CDIM, CDIM, 32);

    // value = input_flatten @ w_val + b_val   (13824 x 768 x 768) -> fp16
    gemm_mma<false, true><<<dim3(CDIM / 128, Mv / 128), 128, SMEM_NP>>>(
        inp, nullptr, wv, b_val, b_val, CDIM, pvh, Mv, CDIM, CDIM);

    // fused [offsets | attn] = query @ [w_off | w_att] + biases  (32768 x 128 x 768)
    gemm_mma<false, false><<<dim3(1, Mq / 128), 128, SMEM_NP>>>(
        query, nullptr, woa, b_off, b_att, 96, poa, Mq, 128, CDIM);

    // softmax + trilinear gather (fp16 value) -> fp16 sampled output
    sample_kernel<<<Mq / 8, 768>>>(refp);

    // out = samp @ w_out + b_out              (32768 x 768 x 768), fp32 out
    gemm_mma<true, false><<<dim3(CDIM / 128, Mq / 128), 128, SMEM_PRE>>>(
        nullptr, sp, wo, b_out, b_out, CDIM, out, Mq, CDIM, CDIM);
}

// round 8
// speedup vs baseline: 5.1530x; 1.0314x over previous
#include <cuda_runtime.h>
#include <cuda_fp16.h>
#include <math.h>
#include <stdint.h>

// Problem constants
#define N_B 8
#define LQ 4096
#define CDIM 768
#define HH 8
#define PP 4
#define DD 96
#define LIN 1728
#define NVOX 12

// ---------------------------------------------------------------------------
// Scratch (static __device__ arrays: allocation-free, graph-capture safe)
// ---------------------------------------------------------------------------
__device__ __half g_valh[(size_t)N_B * LIN * CDIM];      // value (fp16) 21.2 MB
__device__ float g_oa[(size_t)N_B * LQ * 128];           // fused offsets(96)+attn(32)
__device__ __half g_samp[(size_t)N_B * LQ * CDIM];       // sampled (fp16)

// pre-transposed fp16 weights: [N][K]
__device__ __half g_wv[CDIM * CDIM];
__device__ __half g_wo[CDIM * CDIM];
__device__ __half g_woa[128 * CDIM];   // rows 0..95 = w_off, 96..127 = w_att

// ---------------------------------------------------------------------------
// PTX helpers (baseline ISA: ldmatrix + mma.sync + cp.async, sm_80+)
// ---------------------------------------------------------------------------
__device__ __forceinline__ uint32_t smem_u32(const void* p) {
    uint32_t a;
    asm("{ .reg .u64 t; cvta.to.shared.u64 t, %1; cvt.u32.u64 %0, t; }" : "=r"(a) : "l"(p));
    return a;
}
__device__ __forceinline__ void ldmx4(uint32_t& r0, uint32_t& r1, uint32_t& r2,
                                      uint32_t& r3, uint32_t addr) {
    asm volatile("ldmatrix.sync.aligned.m8n8.x4.shared.b16 {%0,%1,%2,%3}, [%4];"
                 : "=r"(r0), "=r"(r1), "=r"(r2), "=r"(r3) : "r"(addr));
}
__device__ __forceinline__ void mma16816(float* d, const uint32_t* a, const uint32_t* b) {
    asm volatile(
        "mma.sync.aligned.m16n8k16.row.col.f32.f16.f16.f32 "
        "{%0,%1,%2,%3}, {%4,%5,%6,%7}, {%8,%9}, {%0,%1,%2,%3};"
        : "+f"(d[0]), "+f"(d[1]), "+f"(d[2]), "+f"(d[3])
        : "r"(a[0]), "r"(a[1]), "r"(a[2]), "r"(a[3]), "r"(b[0]), "r"(b[1]));
}
__device__ __forceinline__ void cpasync16(uint32_t dst, const void* src) {
    asm volatile("cp.async.cg.shared.global [%0], [%1], 16;" :: "r"(dst), "l"(src));
}
#define CP_COMMIT() asm volatile("cp.async.commit_group;" ::: "memory")
#define CP_WAIT(n)  asm volatile("cp.async.wait_group %0;" :: "n"(n) : "memory")

__device__ __forceinline__ uint32_t cvt2(float x, float y) {
    __half2 h = __floats2half2_rn(x, y);
    return *reinterpret_cast<uint32_t*>(&h);
}

// ---------------------------------------------------------------------------
// Coalesced tiled transpose + fp16 convert: h[n*K+k] = (half)w[k*N+n]
// ---------------------------------------------------------------------------
__device__ __forceinline__ void transpose_body(const float* __restrict__ w,
                                               __half* __restrict__ h, int K, int N)
{
    __shared__ float tile[32][33];
    const int k0 = blockIdx.x * 32, n0 = blockIdx.y * 32;
    const int tx = threadIdx.x, ty = threadIdx.y;
    #pragma unroll
    for (int i = 0; i < 32; i += 8)
        tile[ty + i][tx] = w[(size_t)(k0 + ty + i) * N + n0 + tx];
    __syncthreads();
    #pragma unroll
    for (int i = 0; i < 32; i += 8)
        h[(size_t)(n0 + ty + i) * K + k0 + tx] = __float2half(tile[tx][ty + i]);
}
__global__ void transpose_h(const float* __restrict__ w, __half* __restrict__ h,
                            int K, int N)
{
    transpose_body(w, h, K, N);
}
__global__ void transpose_h2(const float* __restrict__ w0, __half* __restrict__ h0,
                             const float* __restrict__ w1, __half* __restrict__ h1)
{
    transpose_body(blockIdx.z ? w1 : w0, blockIdx.z ? h1 : h0, CDIM, CDIM);
}

// ---------------------------------------------------------------------------
// fp16 HMMA GEMM: C[M,128] = A[M,K] @ Bt[128,K]^T + bias
// BM=128, BN=128, BK=32; 256 threads = 4(m) x 2(n) warps; warp tile 32x64.
// __launch_bounds__(256, 2): cap regs at 128 -> 2 blocks/SM, 16 warps/SM.
// PRE=false: A fp32, converted inline; B via cp.async (2-stage).
// PRE=true : A pre-converted fp16; 4-stage all-cp.async pipeline.
// OUTH:     write fp16 output instead of fp32.
// ---------------------------------------------------------------------------
template <bool PRE, bool OUTH>
__global__ void __launch_bounds__(256, 2)
gemm_mma(const float* __restrict__ A32, const __half* __restrict__ Ah,
         const __half* __restrict__ Bt,
         const float* __restrict__ bias, const float* __restrict__ bias2, int nsplit,
         void* __restrict__ Cout, int M, int N, int K)
{
    constexpr int BM = 128, BN = 128, BK = 32, SA = 40;
    constexpr int WN = BN / 2, NF = WN / 8;        // 8 n-frags per warp
    constexpr int A_ELE = BM * SA;
    constexpr int B_ELE = BN * SA;
    constexpr int BUF = A_ELE + B_ELE;
    constexpr int STAGES = PRE ? 4 : 2;

    extern __shared__ __half smbuf[];
    const uint32_t sbase = smem_u32(smbuf);

    const int tid = threadIdx.x;
    const int lane = tid & 31;
    const int wid = tid >> 5;
    const int wm = wid & 3, wn = wid >> 2;
    const int bm = blockIdx.y * BM, bn = blockIdx.x * BN;
    const int nch = K / BK;

    float acc[2][NF][4];
    #pragma unroll
    for (int i = 0; i < 2; i++)
        #pragma unroll
        for (int j = 0; j < NF; j++)
            #pragma unroll
            for (int q = 0; q < 4; q++) acc[i][j][q] = 0.f;

    float4 aR[4];

    auto asyncB = [&](int c, int buf) {
        const int k0 = c * BK;
        const uint32_t base = sbase + (uint32_t)buf * BUF * 2;
        #pragma unroll
        for (int t = 0; t < 2; t++) {
            int l = t * 256 + tid;
            int rr = l >> 2, q = l & 3;
            uint32_t dst = base + (uint32_t)(A_ELE + rr * SA + q * 8) * 2;
            cpasync16(dst, &Bt[(size_t)(bn + rr) * K + k0 + q * 8]);
        }
    };
    auto asyncA = [&](int c, int buf) {    // PRE only
        const int k0 = c * BK;
        const uint32_t base = sbase + (uint32_t)buf * BUF * 2;
        #pragma unroll
        for (int t = 0; t < 2; t++) {
            int l = t * 256 + tid;
            int rr = l >> 2, q = l & 3;
            uint32_t dst = base + (uint32_t)(rr * SA + q * 8) * 2;
            cpasync16(dst, &Ah[(size_t)(bm + rr) * K + k0 + q * 8]);
        }
    };
    auto loadA = [&](int c) {              // !PRE
        const int k0 = c * BK;
        #pragma unroll
        for (int t = 0; t < 4; t++) {
            int l = t * 256 + tid;
            int row = l >> 3, c4 = l & 7;
            aR[t] = *reinterpret_cast<const float4*>(&A32[(size_t)(bm + row) * K + k0 + c4 * 4]);
        }
    };
    auto stsA = [&](int buf) {             // !PRE
        const uint32_t base = sbase + (uint32_t)buf * BUF * 2;
        #pragma unroll
        for (int t = 0; t < 4; t++) {
            int l = t * 256 + tid;
            int row = l >> 3, c4 = l & 7;
            uint32_t a01 = cvt2(aR[t].x, aR[t].y);
            uint32_t a23 = cvt2(aR[t].z, aR[t].w);
            uint32_t off = (uint32_t)(row * SA + c4 * 4) * 2;
            asm volatile("st.shared.v2.b32 [%0], {%1,%2};"
                         :: "r"(base + off), "r"(a01), "r"(a23) : "memory");
        }
    };
    auto compute = [&](int buf) {
        const uint32_t base = sbase + (uint32_t)buf * BUF * 2;
        const uint32_t aS = base;
        const uint32_t bS = base + A_ELE * 2;
        #pragma unroll
        for (int s = 0; s < 2; s++) {
            uint32_t ah[2][4], bh[NF][2];
            #pragma unroll
            for (int i = 0; i < 2; i++) {
                uint32_t row = wm * 32 + i * 16 + (lane & 15);
                uint32_t off = (row * SA + s * 16 + (lane >> 4) * 8) * 2;
                ldmx4(ah[i][0], ah[i][1], ah[i][2], ah[i][3], aS + off);
            }
            #pragma unroll
            for (int j = 0; j < NF; j += 2) {
                uint32_t row = wn * WN + j * 8 + (lane & 7) + ((lane & 16) ? 8 : 0);
                uint32_t off = (row * SA + s * 16 + ((lane >> 3) & 1) * 8) * 2;
                ldmx4(bh[j][0], bh[j][1], bh[j + 1][0], bh[j + 1][1], bS + off);
            }
            #pragma unroll
            for (int i = 0; i < 2; i++)
                #pragma unroll
                for (int j = 0; j < NF; j++)
                    mma16816(acc[i][j], ah[i], bh[j]);
        }
    };

    if constexpr (PRE) {
        #pragma unroll
        for (int i = 0; i < STAGES - 1; i++) {
            asyncA(i, i); asyncB(i, i); CP_COMMIT();
        }
        for (int c = 0; c < nch; c++) {
            CP_WAIT(STAGES - 2);
            __syncthreads();
            int f = c + STAGES - 1;
            if (f < nch) { asyncA(f, f % STAGES); asyncB(f, f % STAGES); }
            CP_COMMIT();
            compute(c % STAGES);
        }
    } else {
        asyncB(0, 0); CP_COMMIT();
        loadA(0);
        CP_WAIT(0);
        stsA(0);
        __syncthreads();
        for (int c = 0; c < nch; c++) {
            if (c + 1 < nch) { asyncB(c + 1, (c + 1) & 1); CP_COMMIT(); loadA(c + 1); }
            compute(c & 1);
            if (c + 1 < nch) { CP_WAIT(0); stsA((c + 1) & 1); }
            __syncthreads();
        }
    }

    // Epilogue: bias add, store fp32 or fp16
    #pragma unroll
    for (int i = 0; i < 2; i++) {
        int r0 = bm + wm * 32 + i * 16 + (lane >> 2);
        #pragma unroll
        for (int j = 0; j < NF; j++) {
            int col = bn + wn * WN + j * 8 + (lane & 3) * 2;
            float b0 = (col < nsplit) ? bias[col] : bias2[col - nsplit];
            float b1 = (col + 1 < nsplit) ? bias[col + 1] : bias2[col + 1 - nsplit];
            if constexpr (OUTH) {
                __half* C = (__half*)Cout;
                uint32_t v0 = cvt2(acc[i][j][0] + b0, acc[i][j][1] + b1);
                uint32_t v1 = cvt2(acc[i][j][2] + b0, acc[i][j][3] + b1);
                *reinterpret_cast<uint32_t*>(&C[(size_t)r0 * N + col]) = v0;
                *reinterpret_cast<uint32_t*>(&C[(size_t)(r0 + 8) * N + col]) = v1;
            } else {
                float* C = (float*)Cout;
                float2 v0 = make_float2(acc[i][j][0] + b0, acc[i][j][1] + b1);
                float2 v1 = make_float2(acc[i][j][2] + b0, acc[i][j][3] + b1);
                *reinterpret_cast<float2*>(&C[(size_t)r0 * N + col]) = v0;
                *reinterpret_cast<float2*>(&C[(size_t)(r0 + 8) * N + col]) = v1;
            }
        }
    }
}

// ---------------------------------------------------------------------------
// Sampler: 768 threads = 8 queries x 96 gather threads (uint4 = 8 fp16 ch).
// ---------------------------------------------------------------------------
__global__ void __launch_bounds__(768) sample_kernel(const float* __restrict__ refpts)
{
    const int b0 = blockIdx.x * 8;

    __shared__ float s_attn[8][32];
    __shared__ int   s_idx[8][32][8];
    __shared__ float s_w[8][32][8];

    const int tid = threadIdx.x;

    if (tid < 256) {
        int qi = tid >> 5, hp = tid & 31;
        int bq = b0 + qi;
        const float* oa = &g_oa[(size_t)bq * 128 + hp * 3];
        float rx = refpts[(size_t)bq * 3 + 0];
        float ry = refpts[(size_t)bq * 3 + 1];
        float rz = refpts[(size_t)bq * 3 + 2];
        float x = 12.f * rx + oa[0] - 0.5f;
        float y = 12.f * ry + oa[1] - 0.5f;
        float z = 12.f * rz + oa[2] - 0.5f;
        float x0f = floorf(x), y0f = floorf(y), z0f = floorf(z);
        int x0 = (int)x0f, y0 = (int)y0f, z0 = (int)z0f;
        float fx = x - x0f, fy = y - y0f, fz = z - z0f;
        #pragma unroll
        for (int c = 0; c < 8; c++) {
            int dx = c & 1, dy = (c >> 1) & 1, dz = (c >> 2) & 1;
            int xi = x0 + dx, yi = y0 + dy, zi = z0 + dz;
            float w = (dx ? fx : 1.f - fx) * (dy ? fy : 1.f - fy) * (dz ? fz : 1.f - fz);
            bool valid = (xi >= 0) & (xi < NVOX) & (yi >= 0) & (yi < NVOX) &
                         (zi >= 0) & (zi < NVOX);
            int xc = min(max(xi, 0), NVOX - 1);
            int yc = min(max(yi, 0), NVOX - 1);
            int zc = min(max(zi, 0), NVOX - 1);
            s_idx[qi][hp][c] = (zc * NVOX + yc) * NVOX + xc;
            s_w[qi][hp][c] = valid ? w : 0.f;
        }
    }
    if (tid >= 256 && tid < 320) {
        int idx = tid - 256;
        int qi = idx >> 3, h = idx & 7;
        const float* lg = &g_oa[(size_t)(b0 + qi) * 128 + 96 + h * 4];
        float m = fmaxf(fmaxf(lg[0], lg[1]), fmaxf(lg[2], lg[3]));
        float e0 = expf(lg[0] - m), e1 = expf(lg[1] - m);
        float e2 = expf(lg[2] - m), e3 = expf(lg[3] - m);
        float inv = 1.f / (e0 + e1 + e2 + e3);
        s_attn[qi][h * 4 + 0] = e0 * inv;
        s_attn[qi][h * 4 + 1] = e1 * inv;
        s_attn[qi][h * 4 + 2] = e2 * inv;
        s_attn[qi][h * 4 + 3] = e3 * inv;
    }
    __syncthreads();

    const int qi = tid / 96;
    const int tt = tid % 96;
    const int h = tt / 12;
    const int c8 = (tt % 12) * 8;
    const int bq = b0 + qi;
    const int n = bq >> 12;
    const __half* vbase = &g_valh[(size_t)n * LIN * CDIM + h * DD + c8];

    float acc[8];
    #pragma unroll
    for (int k = 0; k < 8; k++) acc[k] = 0.f;

    #pragma unroll
    for (int p = 0; p < PP; p++) {
        int hp = h * PP + p;
        float a = s_attn[qi][hp];
        float sv[8];
        #pragma unroll
        for (int k = 0; k < 8; k++) sv[k] = 0.f;
        #pragma unroll
        for (int c = 0; c < 8; c++) {
            float w = s_w[qi][hp][c];
            uint4 v = *reinterpret_cast<const uint4*>(
                vbase + (size_t)s_idx[qi][hp][c] * CDIM);
            const __half2* hv = reinterpret_cast<const __half2*>(&v);
            #pragma unroll
            for (int k = 0; k < 4; k++) {
                float2 f = __half22float2(hv[k]);
                sv[2 * k]     = fmaf(w, f.x, sv[2 * k]);
                sv[2 * k + 1] = fmaf(w, f.y, sv[2 * k + 1]);
            }
        }
        #pragma unroll
        for (int k = 0; k < 8; k++) acc[k] = fmaf(a, sv[k], acc[k]);
    }

    uint4 o;
    o.x = cvt2(acc[0], acc[1]);
    o.y = cvt2(acc[2], acc[3]);
    o.z = cvt2(acc[4], acc[5]);
    o.w = cvt2(acc[6], acc[7]);
    *reinterpret_cast<uint4*>(&g_samp[(size_t)bq * CDIM + h * DD + c8]) = o;
}

// ---------------------------------------------------------------------------
// Launch
// ---------------------------------------------------------------------------
extern "C" void kernel_launch(void* const* d_in, const int* in_sizes, int n_in,
                              void* d_out, int out_size)
{
    const float* query = (const float*)d_in[0];
    const float* refp  = (const float*)d_in[1];
    const float* inp   = (const float*)d_in[2];
    const float* w_val = (const float*)d_in[3];
    const float* b_val = (const float*)d_in[4];
    const float* w_off = (const float*)d_in[5];
    const float* b_off = (const float*)d_in[6];
    const float* w_att = (const float*)d_in[7];
    const float* b_att = (const float*)d_in[8];
    const float* w_out = (const float*)d_in[9];
    const float* b_out = (const float*)d_in[10];
    float* out = (float*)d_out;

    float* poa;
    cudaGetSymbolAddress((void**)&poa, g_oa);
    __half *pvh, *sp, *wv, *wo, *woa;
    cudaGetSymbolAddress((void**)&pvh, g_valh);
    cudaGetSymbolAddress((void**)&sp, g_samp);
    cudaGetSymbolAddress((void**)&wv, g_wv);
    cudaGetSymbolAddress((void**)&wo, g_wo);
    cudaGetSymbolAddress((void**)&woa, g_woa);

    const int SMEM_NP  = 2 * 20480;   // 40 KB (2-stage)
    const int SMEM_PRE = 4 * 20480;   // 80 KB (4-stage)
    cudaFuncSetAttribute((const void*)gemm_mma<false, true>,
                         cudaFuncAttributeMaxDynamicSharedMemorySize, SMEM_NP);
    cudaFuncSetAttribute((const void*)gemm_mma<false, false>,
                         cudaFuncAttributeMaxDynamicSharedMemorySize, SMEM_NP);
    cudaFuncSetAttribute((const void*)gemm_mma<true, false>,
                         cudaFuncAttributeMaxDynamicSharedMemorySize, SMEM_PRE);

    const int Mv = N_B * LIN;   // 13824
    const int Mq = N_B * LQ;    // 32768

    // weight transpose + fp16 convert (wv + wo fused into one launch)
    transpose_h2<<<dim3(CDIM / 32, CDIM / 32, 2), dim3(32, 8)>>>(w_val, wv, w_out, wo);
    transpose_h<<<dim3(CDIM / 32, 96 / 32), dim3(32, 8)>>>(w_off, woa, CDIM, 96);
    transpose_h<<<dim3(CDIM / 32, 32 / 32), dim3(32, 8)>>>(w_att, woa + 96 * CDIM, CDIM, 32);

    // value = input_flatten @ w_val + b_val   (13824 x 768 x 768) -> fp16
    gemm_mma<false, true><<<dim3(CDIM / 128, Mv / 128), 256, SMEM_NP>>>(
        inp, nullptr, wv, b_val, b_val, CDIM, pvh, Mv, CDIM, CDIM);

    // fused [offsets | attn] = query @ [w_off | w_att] + biases  (32768 x 128 x 768)
    gemm_mma<false, false><<<dim3(1, Mq / 128), 256, SMEM_NP>>>(
        query, nullptr, woa, b_off, b_att, 96, poa, Mq, 128, CDIM);

    // softmax + trilinear gather (fp16 value) -> fp16 sampled output
    sample_kernel<<<Mq / 8, 768>>>(refp);

    // out = samp @ w_out + b_out              (32768 x 768 x 768), fp32 out
    gemm_mma<true, false><<<dim3(CDIM / 128, Mq / 128), 256, SMEM_PRE>>>(
        nullptr, sp, wo, b_out, b_out, CDIM, out, Mq, CDIM, CDIM);
}

// round 9
// speedup vs baseline: 5.1565x; 1.0007x over previous
#include <cuda_runtime.h>
#include <cuda_fp16.h>
#include <math.h>
#include <stdint.h>

// Problem constants
#define N_B 8
#define LQ 4096
#define CDIM 768
#define HH 8
#define PP 4
#define DD 96
#define LIN 1728
#define NVOX 12

// ---------------------------------------------------------------------------
// Scratch (static __device__ arrays: allocation-free, graph-capture safe)
// ---------------------------------------------------------------------------
__device__ __half g_inph[(size_t)N_B * LIN * CDIM];      // input_flatten (fp16)
__device__ __half g_valh[(size_t)N_B * LIN * CDIM];      // value (fp16) 21.2 MB
__device__ float g_oa[(size_t)N_B * LQ * 128];           // fused offsets(96)+attn(32)
__device__ __half g_samp[(size_t)N_B * LQ * CDIM];       // sampled (fp16)

// pre-transposed fp16 weights: [N][K]
__device__ __half g_wv[CDIM * CDIM];
__device__ __half g_wo[CDIM * CDIM];
__device__ __half g_woa[128 * CDIM];   // rows 0..95 = w_off, 96..127 = w_att

// ---------------------------------------------------------------------------
// PTX helpers (baseline ISA: ldmatrix + mma.sync + cp.async, sm_80+)
// ---------------------------------------------------------------------------
__device__ __forceinline__ uint32_t smem_u32(const void* p) {
    uint32_t a;
    asm("{ .reg .u64 t; cvta.to.shared.u64 t, %1; cvt.u32.u64 %0, t; }" : "=r"(a) : "l"(p));
    return a;
}
__device__ __forceinline__ void ldmx4(uint32_t& r0, uint32_t& r1, uint32_t& r2,
                                      uint32_t& r3, uint32_t addr) {
    asm volatile("ldmatrix.sync.aligned.m8n8.x4.shared.b16 {%0,%1,%2,%3}, [%4];"
                 : "=r"(r0), "=r"(r1), "=r"(r2), "=r"(r3) : "r"(addr));
}
__device__ __forceinline__ void mma16816(float* d, const uint32_t* a, const uint32_t* b) {
    asm volatile(
        "mma.sync.aligned.m16n8k16.row.col.f32.f16.f16.f32 "
        "{%0,%1,%2,%3}, {%4,%5,%6,%7}, {%8,%9}, {%0,%1,%2,%3};"
        : "+f"(d[0]), "+f"(d[1]), "+f"(d[2]), "+f"(d[3])
        : "r"(a[0]), "r"(a[1]), "r"(a[2]), "r"(a[3]), "r"(b[0]), "r"(b[1]));
}
__device__ __forceinline__ void cpasync16(uint32_t dst, const void* src) {
    asm volatile("cp.async.cg.shared.global [%0], [%1], 16;" :: "r"(dst), "l"(src));
}
#define CP_COMMIT() asm volatile("cp.async.commit_group;" ::: "memory")
#define CP_WAIT(n)  asm volatile("cp.async.wait_group %0;" :: "n"(n) : "memory")

__device__ __forceinline__ uint32_t cvt2(float x, float y) {
    __half2 h = __floats2half2_rn(x, y);
    return *reinterpret_cast<uint32_t*>(&h);
}

// ---------------------------------------------------------------------------
// Bulk fp32 -> fp16 convert (8 elems/thread, vectorized)
// ---------------------------------------------------------------------------
__global__ void f2h(const float* __restrict__ in, __half* __restrict__ out, int n)
{
    int i = (blockIdx.x * 256 + threadIdx.x) * 8;
    if (i >= n) return;
    float4 a = *reinterpret_cast<const float4*>(in + i);
    float4 b = *reinterpret_cast<const float4*>(in + i + 4);
    uint4 o;
    o.x = cvt2(a.x, a.y);
    o.y = cvt2(a.z, a.w);
    o.z = cvt2(b.x, b.y);
    o.w = cvt2(b.z, b.w);
    *reinterpret_cast<uint4*>(out + i) = o;
}

// ---------------------------------------------------------------------------
// Coalesced tiled transpose + fp16 convert: h[n*K+k] = (half)w[k*N+n]
// ---------------------------------------------------------------------------
__device__ __forceinline__ void transpose_body(const float* __restrict__ w,
                                               __half* __restrict__ h, int K, int N)
{
    __shared__ float tile[32][33];
    const int k0 = blockIdx.x * 32, n0 = blockIdx.y * 32;
    const int tx = threadIdx.x, ty = threadIdx.y;
    #pragma unroll
    for (int i = 0; i < 32; i += 8)
        tile[ty + i][tx] = w[(size_t)(k0 + ty + i) * N + n0 + tx];
    __syncthreads();
    #pragma unroll
    for (int i = 0; i < 32; i += 8)
        h[(size_t)(n0 + ty + i) * K + k0 + tx] = __float2half(tile[tx][ty + i]);
}
__global__ void transpose_h(const float* __restrict__ w, __half* __restrict__ h,
                            int K, int N)
{
    transpose_body(w, h, K, N);
}
__global__ void transpose_h2(const float* __restrict__ w0, __half* __restrict__ h0,
                             const float* __restrict__ w1, __half* __restrict__ h1)
{
    transpose_body(blockIdx.z ? w1 : w0, blockIdx.z ? h1 : h0, CDIM, CDIM);
}

// ---------------------------------------------------------------------------
// fp16 HMMA GEMM: C[M,128] = A[M,K] @ Bt[128,K]^T + bias
// BM=128, BN=128, BK=32; 256 threads = 4(m) x 2(n) warps; warp tile 32x64.
// __launch_bounds__(256, 2): cap regs at 128 -> 2 blocks/SM, 16 warps/SM.
// PRE=false: A fp32, converted inline; B via cp.async (2-stage).
// PRE=true : A pre-converted fp16; 4-stage all-cp.async pipeline.
// OUTH:     write fp16 output instead of fp32.
// ---------------------------------------------------------------------------
template <bool PRE, bool OUTH>
__global__ void __launch_bounds__(256, 2)
gemm_mma(const float* __restrict__ A32, const __half* __restrict__ Ah,
         const __half* __restrict__ Bt,
         const float* __restrict__ bias, const float* __restrict__ bias2, int nsplit,
         void* __restrict__ Cout, int M, int N, int K)
{
    constexpr int BM = 128, BN = 128, BK = 32, SA = 40;
    constexpr int WN = BN / 2, NF = WN / 8;        // 8 n-frags per warp
    constexpr int A_ELE = BM * SA;
    constexpr int B_ELE = BN * SA;
    constexpr int BUF = A_ELE + B_ELE;
    constexpr int STAGES = PRE ? 4 : 2;

    extern __shared__ __half smbuf[];
    const uint32_t sbase = smem_u32(smbuf);

    const int tid = threadIdx.x;
    const int lane = tid & 31;
    const int wid = tid >> 5;
    const int wm = wid & 3, wn = wid >> 2;
    const int bm = blockIdx.y * BM, bn = blockIdx.x * BN;
    const int nch = K / BK;

    float acc[2][NF][4];
    #pragma unroll
    for (int i = 0; i < 2; i++)
        #pragma unroll
        for (int j = 0; j < NF; j++)
            #pragma unroll
            for (int q = 0; q < 4; q++) acc[i][j][q] = 0.f;

    float4 aR[4];

    auto asyncB = [&](int c, int buf) {
        const int k0 = c * BK;
        const uint32_t base = sbase + (uint32_t)buf * BUF * 2;
        #pragma unroll
        for (int t = 0; t < 2; t++) {
            int l = t * 256 + tid;
            int rr = l >> 2, q = l & 3;
            uint32_t dst = base + (uint32_t)(A_ELE + rr * SA + q * 8) * 2;
            cpasync16(dst, &Bt[(size_t)(bn + rr) * K + k0 + q * 8]);
        }
    };
    auto asyncA = [&](int c, int buf) {    // PRE only
        const int k0 = c * BK;
        const uint32_t base = sbase + (uint32_t)buf * BUF * 2;
        #pragma unroll
        for (int t = 0; t < 2; t++) {
            int l = t * 256 + tid;
            int rr = l >> 2, q = l & 3;
            uint32_t dst = base + (uint32_t)(rr * SA + q * 8) * 2;
            cpasync16(dst, &Ah[(size_t)(bm + rr) * K + k0 + q * 8]);
        }
    };
    auto loadA = [&](int c) {              // !PRE
        const int k0 = c * BK;
        #pragma unroll
        for (int t = 0; t < 4; t++) {
            int l = t * 256 + tid;
            int row = l >> 3, c4 = l & 7;
            aR[t] = *reinterpret_cast<const float4*>(&A32[(size_t)(bm + row) * K + k0 + c4 * 4]);
        }
    };
    auto stsA = [&](int buf) {             // !PRE
        const uint32_t base = sbase + (uint32_t)buf * BUF * 2;
        #pragma unroll
        for (int t = 0; t < 4; t++) {
            int l = t * 256 + tid;
            int row = l >> 3, c4 = l & 7;
            uint32_t a01 = cvt2(aR[t].x, aR[t].y);
            uint32_t a23 = cvt2(aR[t].z, aR[t].w);
            uint32_t off = (uint32_t)(row * SA + c4 * 4) * 2;
            asm volatile("st.shared.v2.b32 [%0], {%1,%2};"
                         :: "r"(base + off), "r"(a01), "r"(a23) : "memory");
        }
    };
    auto compute = [&](int buf) {
        const uint32_t base = sbase + (uint32_t)buf * BUF * 2;
        const uint32_t aS = base;
        const uint32_t bS = base + A_ELE * 2;
        #pragma unroll
        for (int s = 0; s < 2; s++) {
            uint32_t ah[2][4], bh[NF][2];
            #pragma unroll
            for (int i = 0; i < 2; i++) {
                uint32_t row = wm * 32 + i * 16 + (lane & 15);
                uint32_t off = (row * SA + s * 16 + (lane >> 4) * 8) * 2;
                ldmx4(ah[i][0], ah[i][1], ah[i][2], ah[i][3], aS + off);
            }
            #pragma unroll
            for (int j = 0; j < NF; j += 2) {
                uint32_t row = wn * WN + j * 8 + (lane & 7) + ((lane & 16) ? 8 : 0);
                uint32_t off = (row * SA + s * 16 + ((lane >> 3) & 1) * 8) * 2;
                ldmx4(bh[j][0], bh[j][1], bh[j + 1][0], bh[j + 1][1], bS + off);
            }
            #pragma unroll
            for (int i = 0; i < 2; i++)
                #pragma unroll
                for (int j = 0; j < NF; j++)
                    mma16816(acc[i][j], ah[i], bh[j]);
        }
    };

    if constexpr (PRE) {
        #pragma unroll
        for (int i = 0; i < STAGES - 1; i++) {
            asyncA(i, i); asyncB(i, i); CP_COMMIT();
        }
        for (int c = 0; c < nch; c++) {
            CP_WAIT(STAGES - 2);
            __syncthreads();
            int f = c + STAGES - 1;
            if (f < nch) { asyncA(f, f % STAGES); asyncB(f, f % STAGES); }
            CP_COMMIT();
            compute(c % STAGES);
        }
    } else {
        asyncB(0, 0); CP_COMMIT();
        loadA(0);
        CP_WAIT(0);
        stsA(0);
        __syncthreads();
        for (int c = 0; c < nch; c++) {
            if (c + 1 < nch) { asyncB(c + 1, (c + 1) & 1); CP_COMMIT(); loadA(c + 1); }
            compute(c & 1);
            if (c + 1 < nch) { CP_WAIT(0); stsA((c + 1) & 1); }
            __syncthreads();
        }
    }

    // Epilogue: bias add, store fp32 or fp16
    #pragma unroll
    for (int i = 0; i < 2; i++) {
        int r0 = bm + wm * 32 + i * 16 + (lane >> 2);
        #pragma unroll
        for (int j = 0; j < NF; j++) {
            int col = bn + wn * WN + j * 8 + (lane & 3) * 2;
            float b0 = (col < nsplit) ? bias[col] : bias2[col - nsplit];
            float b1 = (col + 1 < nsplit) ? bias[col + 1] : bias2[col + 1 - nsplit];
            if constexpr (OUTH) {
                __half* C = (__half*)Cout;
                uint32_t v0 = cvt2(acc[i][j][0] + b0, acc[i][j][1] + b1);
                uint32_t v1 = cvt2(acc[i][j][2] + b0, acc[i][j][3] + b1);
                *reinterpret_cast<uint32_t*>(&C[(size_t)r0 * N + col]) = v0;
                *reinterpret_cast<uint32_t*>(&C[(size_t)(r0 + 8) * N + col]) = v1;
            } else {
                float* C = (float*)Cout;
                float2 v0 = make_float2(acc[i][j][0] + b0, acc[i][j][1] + b1);
                float2 v1 = make_float2(acc[i][j][2] + b0, acc[i][j][3] + b1);
                *reinterpret_cast<float2*>(&C[(size_t)r0 * N + col]) = v0;
                *reinterpret_cast<float2*>(&C[(size_t)(r0 + 8) * N + col]) = v1;
            }
        }
    }
}

// ---------------------------------------------------------------------------
// Sampler: 768 threads = 8 queries x 96 gather threads (uint4 = 8 fp16 ch).
// ---------------------------------------------------------------------------
__global__ void __launch_bounds__(768) sample_kernel(const float* __restrict__ refpts)
{
    const int b0 = blockIdx.x * 8;

    __shared__ float s_attn[8][32];
    __shared__ int   s_idx[8][32][8];
    __shared__ float s_w[8][32][8];

    const int tid = threadIdx.x;

    if (tid < 256) {
        int qi = tid >> 5, hp = tid & 31;
        int bq = b0 + qi;
        const float* oa = &g_oa[(size_t)bq * 128 + hp * 3];
        float rx = refpts[(size_t)bq * 3 + 0];
        float ry = refpts[(size_t)bq * 3 + 1];
        float rz = refpts[(size_t)bq * 3 + 2];
        float x = 12.f * rx + oa[0] - 0.5f;
        float y = 12.f * ry + oa[1] - 0.5f;
        float z = 12.f * rz + oa[2] - 0.5f;
        float x0f = floorf(x), y0f = floorf(y), z0f = floorf(z);
        int x0 = (int)x0f, y0 = (int)y0f, z0 = (int)z0f;
        float fx = x - x0f, fy = y - y0f, fz = z - z0f;
        #pragma unroll
        for (int c = 0; c < 8; c++) {
            int dx = c & 1, dy = (c >> 1) & 1, dz = (c >> 2) & 1;
            int xi = x0 + dx, yi = y0 + dy, zi = z0 + dz;
            float w = (dx ? fx : 1.f - fx) * (dy ? fy : 1.f - fy) * (dz ? fz : 1.f - fz);
            bool valid = (xi >= 0) & (xi < NVOX) & (yi >= 0) & (yi < NVOX) &
                         (zi >= 0) & (zi < NVOX);
            int xc = min(max(xi, 0), NVOX - 1);
            int yc = min(max(yi, 0), NVOX - 1);
            int zc = min(max(zi, 0), NVOX - 1);
            s_idx[qi][hp][c] = (zc * NVOX + yc) * NVOX + xc;
            s_w[qi][hp][c] = valid ? w : 0.f;
        }
    }
    if (tid >= 256 && tid < 320) {
        int idx = tid - 256;
        int qi = idx >> 3, h = idx & 7;
        const float* lg = &g_oa[(size_t)(b0 + qi) * 128 + 96 + h * 4];
        float m = fmaxf(fmaxf(lg[0], lg[1]), fmaxf(lg[2], lg[3]));
        float e0 = expf(lg[0] - m), e1 = expf(lg[1] - m);
        float e2 = expf(lg[2] - m), e3 = expf(lg[3] - m);
        float inv = 1.f / (e0 + e1 + e2 + e3);
        s_attn[qi][h * 4 + 0] = e0 * inv;
        s_attn[qi][h * 4 + 1] = e1 * inv;
        s_attn[qi][h * 4 + 2] = e2 * inv;
        s_attn[qi][h * 4 + 3] = e3 * inv;
    }
    __syncthreads();

    const int qi = tid / 96;
    const int tt = tid % 96;
    const int h = tt / 12;
    const int c8 = (tt % 12) * 8;
    const int bq = b0 + qi;
    const int n = bq >> 12;
    const __half* vbase = &g_valh[(size_t)n * LIN * CDIM + h * DD + c8];

    float acc[8];
    #pragma unroll
    for (int k = 0; k < 8; k++) acc[k] = 0.f;

    #pragma unroll
    for (int p = 0; p < PP; p++) {
        int hp = h * PP + p;
        float a = s_attn[qi][hp];
        float sv[8];
        #pragma unroll
        for (int k = 0; k < 8; k++) sv[k] = 0.f;
        #pragma unroll
        for (int c = 0; c < 8; c++) {
            float w = s_w[qi][hp][c];
            uint4 v = *reinterpret_cast<const uint4*>(
                vbase + (size_t)s_idx[qi][hp][c] * CDIM);
            const __half2* hv = reinterpret_cast<const __half2*>(&v);
            #pragma unroll
            for (int k = 0; k < 4; k++) {
                float2 f = __half22float2(hv[k]);
                sv[2 * k]     = fmaf(w, f.x, sv[2 * k]);
                sv[2 * k + 1] = fmaf(w, f.y, sv[2 * k + 1]);
            }
        }
        #pragma unroll
        for (int k = 0; k < 8; k++) acc[k] = fmaf(a, sv[k], acc[k]);
    }

    uint4 o;
    o.x = cvt2(acc[0], acc[1]);
    o.y = cvt2(acc[2], acc[3]);
    o.z = cvt2(acc[4], acc[5]);
    o.w = cvt2(acc[6], acc[7]);
    *reinterpret_cast<uint4*>(&g_samp[(size_t)bq * CDIM + h * DD + c8]) = o;
}

// ---------------------------------------------------------------------------
// Launch
// ---------------------------------------------------------------------------
extern "C" void kernel_launch(void* const* d_in, const int* in_sizes, int n_in,
                              void* d_out, int out_size)
{
    const float* query = (const float*)d_in[0];
    const float* refp  = (const float*)d_in[1];
    const float* inp   = (const float*)d_in[2];
    const float* w_val = (const float*)d_in[3];
    const float* b_val = (const float*)d_in[4];
    const float* w_off = (const float*)d_in[5];
    const float* b_off = (const float*)d_in[6];
    const float* w_att = (const float*)d_in[7];
    const float* b_att = (const float*)d_in[8];
    const float* w_out = (const float*)d_in[9];
    const float* b_out = (const float*)d_in[10];
    float* out = (float*)d_out;

    float* poa;
    cudaGetSymbolAddress((void**)&poa, g_oa);
    __half *pih, *pvh, *sp, *wv, *wo, *woa;
    cudaGetSymbolAddress((void**)&pih, g_inph);
    cudaGetSymbolAddress((void**)&pvh, g_valh);
    cudaGetSymbolAddress((void**)&sp, g_samp);
    cudaGetSymbolAddress((void**)&wv, g_wv);
    cudaGetSymbolAddress((void**)&wo, g_wo);
    cudaGetSymbolAddress((void**)&woa, g_woa);

    const int SMEM_NP  = 2 * 20480;   // 40 KB (2-stage)
    const int SMEM_PRE = 4 * 20480;   // 80 KB (4-stage)
    cudaFuncSetAttribute((const void*)gemm_mma<false, false>,
                         cudaFuncAttributeMaxDynamicSharedMemorySize, SMEM_NP);
    cudaFuncSetAttribute((const void*)gemm_mma<true, true>,
                         cudaFuncAttributeMaxDynamicSharedMemorySize, SMEM_PRE);
    cudaFuncSetAttribute((const void*)gemm_mma<true, false>,
                         cudaFuncAttributeMaxDynamicSharedMemorySize, SMEM_PRE);

    const int Mv = N_B * LIN;   // 13824
    const int Mq = N_B * LQ;    // 32768

    // weight transpose + fp16 convert (wv + wo fused into one launch)
    transpose_h2<<<dim3(CDIM / 32, CDIM / 32, 2), dim3(32, 8)>>>(w_val, wv, w_out, wo);
    transpose_h<<<dim3(CDIM / 32, 96 / 32), dim3(32, 8)>>>(w_off, woa, CDIM, 96);
    transpose_h<<<dim3(CDIM / 32, 32 / 32), dim3(32, 8)>>>(w_att, woa + 96 * CDIM, CDIM, 32);

    // pre-convert input_flatten to fp16 (read 6x by the value GEMM)
    f2h<<<(Mv * CDIM) / (256 * 8), 256>>>(inp, pih, Mv * CDIM);

    // value = input_flatten @ w_val + b_val   (13824 x 768 x 768) -> fp16, PRE pipeline
    gemm_mma<true, true><<<dim3(CDIM / 128, Mv / 128), 256, SMEM_PRE>>>(
        nullptr, pih, wv, b_val, b_val, CDIM, pvh, Mv, CDIM, CDIM);

    // fused [offsets | attn] = query @ [w_off | w_att] + biases  (32768 x 128 x 768)
    gemm_mma<false, false><<<dim3(1, Mq / 128), 256, SMEM_NP>>>(
        query, nullptr, woa, b_off, b_att, 96, poa, Mq, 128, CDIM);

    // softmax + trilinear gather (fp16 value) -> fp16 sampled output
    sample_kernel<<<Mq / 8, 768>>>(refp);

    // out = samp @ w_out + b_out              (32768 x 768 x 768), fp32 out
    gemm_mma<true, false><<<dim3(CDIM / 128, Mq / 128), 256, SMEM_PRE>>>(
        nullptr, sp, wo, b_out, b_out, CDIM, out, Mq, CDIM, CDIM);
}